// round 1
// baseline (speedup 1.0000x reference)
#include <cuda_runtime.h>
#include <cuda_bf16.h>
#include <math.h>

#define PI_D 3.14159265358979323846

// ---------------- sizes ----------------
#define BATCH 128
#define NB_IN 60      // 2*B_IN beta points
#define NA_IN 60      // alpha points
#define NM1 19        // retained m freqs for B1 (m=-9..9)
#define NL1 10        // l = 0..9
#define NF1 20        // F1 channels
#define NB1 20        // 2*B1
#define NM2 11        // retained freqs for B2 (m=-5..5)
#define NL2 6
#define NF2 40
#define NB2 12        // 2*B2

// ---------------- device scratch / constants ----------------
__device__ double g_lf[64];
__device__ double g_w30[60];
__device__ double g_w10[20];
__device__ float  g_w2n[12];

__device__ float2 g_T60[NM1 * 60];       // e^{-2pi i m a /60}, m=mi-9
__device__ float2 g_E20P[NM1 * 20];      // e^{+2pi i n x /20}, n=ni-9
__device__ float2 g_E20M[NM2 * 20];      // e^{-2pi i m x /20}, m=mi-5
__device__ float2 g_E12P[NM2 * 12];      // e^{+2pi i n x /12}, n=ni-5

__device__ float  g_wd_s2[NL1 * NB_IN * NM1];      // [l][b][mi]
__device__ float  g_d1w[NL1 * NB1 * NM1 * NM1];    // [l][b][mi][ni]
__device__ float  g_d12w[NL2 * NB1 * NM2 * NM2];   // [l][b][mi][ni]
__device__ float  g_d2w[NL2 * NB2 * NM2 * NM2];    // [l][b][mi][ni]
__device__ float2 g_Y1[NL1 * 24 * NM1];            // [l][g][mi]
__device__ float2 g_D2[NL2 * 144 * NM2 * NM2];     // [l][g][mi][ni]

__device__ float2 g_Psi1[NL1 * NF1 * NM1];         // [l][o][ni]
__device__ float2 g_E1[NF1 * NB1 * NL1 * NM1 * 20];// [o][b][l][mi][g]
__device__ float2 g_X[BATCH * NL1 * NM1];          // [z][l][mi]
__device__ float2 g_S1[(size_t)BATCH * NF1 * NB1 * NM1 * 20]; // [z][o][b][mi][g]
__device__ float2 g_Yg[(size_t)BATCH * NF1 * NB1 * NM2 * NM2]; // [z][c][b][mi][ni]
__device__ float2 g_Fx[(size_t)NL2 * NM2 * BATCH * NF1 * NM2]; // [(l*11+mi)][z][i*11+ki]
__device__ float2 g_B2[(size_t)NL2 * 220 * 440];   // [l][ik][on]
__device__ float2 g_Fo[(size_t)BATCH * NF2 * NL2 * NM2 * NM2]; // [z][o][l][mi][ni]
__device__ float  g_feat[BATCH * NF2];

// ---------------- helpers ----------------
__device__ __forceinline__ float2 cmulf(float2 a, float2 b) {
    return make_float2(a.x * b.x - a.y * b.y, a.x * b.y + a.y * b.x);
}

__device__ __forceinline__ double dpow_i(double x, int p) {
    double r = 1.0;
    for (int i = 0; i < p; ++i) r *= x;
    return r;
}

__device__ double wigd(int l, int m, int n, double beta) {
    if (m > l || m < -l || n > l || n < -l) return 0.0;
    double cb = cos(0.5 * beta), sb = sin(0.5 * beta);
    double pref = 0.5 * (g_lf[l + m] + g_lf[l - m] + g_lf[l + n] + g_lf[l - n]);
    int s0 = max(0, n - m), s1 = min(l + n, l - m);
    double acc = 0.0;
    for (int s = s0; s <= s1; ++s) {
        double c = pref - (g_lf[l + n - s] + g_lf[s] + g_lf[m - n + s] + g_lf[l - m - s]);
        double t = exp(c) * dpow_i(cb, 2 * l + n - m - 2 * s) * dpow_i(sb, m - n + 2 * s);
        acc += ((m - n + s) & 1) ? -t : t;
    }
    return acc;
}

__device__ double dh_w_val(int bsz, int k) {
    double beta = PI_D * (2 * k + 1) / (4.0 * bsz);
    double s = 0.0;
    for (int j = 0; j < bsz; ++j)
        s += sin((2 * j + 1) * beta) / (2 * j + 1);
    return (2.0 / bsz) * sin(beta) * s;
}

// ---------------- setup 1: weights, log-factorials, twiddles ----------------
__global__ void k_setup1() {
    int idx = blockIdx.x * blockDim.x + threadIdx.x;
    if (idx < 1140) { // T60
        int mi = idx / 60, a = idx % 60;
        double th = -2.0 * PI_D * (mi - 9) * a / 60.0;
        g_T60[idx] = make_float2((float)cos(th), (float)sin(th));
    } else if (idx < 1520) { // E20P
        int r = idx - 1140; int ni = r / 20, x = r % 20;
        double th = 2.0 * PI_D * (ni - 9) * x / 20.0;
        g_E20P[r] = make_float2((float)cos(th), (float)sin(th));
    } else if (idx < 1740) { // E20M
        int r = idx - 1520; int mi = r / 20, x = r % 20;
        double th = -2.0 * PI_D * (mi - 5) * x / 20.0;
        g_E20M[r] = make_float2((float)cos(th), (float)sin(th));
    } else if (idx < 1872) { // E12P
        int r = idx - 1740; int ni = r / 12, x = r % 12;
        double th = 2.0 * PI_D * (ni - 5) * x / 12.0;
        g_E12P[r] = make_float2((float)cos(th), (float)sin(th));
    } else if (idx < 1932) { // w30
        int k = idx - 1872;
        g_w30[k] = dh_w_val(30, k);
    } else if (idx < 1952) { // w10
        int k = idx - 1932;
        g_w10[k] = dh_w_val(10, k);
    } else if (idx < 1964) { // w2n (normalized dh_w(6))
        int k = idx - 1952;
        double s = 0.0;
        for (int j = 0; j < 12; ++j) s += dh_w_val(6, j);
        g_w2n[k] = (float)(dh_w_val(6, k) / s);
    } else if (idx < 2005) { // lf
        int n = idx - 1964;
        g_lf[n] = lgamma(n + 1.0);
    }
}

// ---------------- setup 2: wigner-d based tables ----------------
#define O_WDS2 0
#define N_WDS2 (NL1*NB_IN*NM1)               // 11400
#define O_D1W  (O_WDS2 + N_WDS2)             // 11400
#define N_D1W  (NL1*NB1*NM1*NM1)             // 72200
#define O_D12W (O_D1W + N_D1W)               // 83600
#define N_D12W (NL2*NB1*NM2*NM2)             // 14520
#define O_D2W  (O_D12W + N_D12W)             // 98120
#define N_D2W  (NL2*NB2*NM2*NM2)             // 8712
#define O_Y1   (O_D2W + N_D2W)               // 106832
#define N_Y1   (NL1*24*NM1)                  // 4560
#define O_D2   (O_Y1 + N_Y1)                 // 111392
#define N_D2   (NL2*144*NM2*NM2)             // 104544
#define N_SET2 (O_D2 + N_D2)                 // 215936

__global__ void k_setup2() {
    int idx = blockIdx.x * blockDim.x + threadIdx.x;
    if (idx >= N_SET2) return;
    if (idx < O_D1W) {
        int i = idx - O_WDS2;
        int l = i / (NB_IN * NM1); int r = i % (NB_IN * NM1);
        int b = r / NM1, mi = r % NM1;
        double beta = PI_D * (2 * b + 1) / 120.0;
        g_wd_s2[i] = (float)(g_w30[b] * wigd(l, mi - 9, 0, beta));
    } else if (idx < O_D12W) {
        int i = idx - O_D1W;
        int l = i / (NB1 * NM1 * NM1); int r = i % (NB1 * NM1 * NM1);
        int b = r / (NM1 * NM1); int q = r % (NM1 * NM1);
        int mi = q / NM1, ni = q % NM1;
        double beta = PI_D * (2 * b + 1) / 40.0;
        g_d1w[i] = (float)((2 * l + 1) * wigd(l, mi - 9, ni - 9, beta));
    } else if (idx < O_D2W) {
        int i = idx - O_D12W;
        int l = i / (NB1 * NM2 * NM2); int r = i % (NB1 * NM2 * NM2);
        int b = r / (NM2 * NM2); int q = r % (NM2 * NM2);
        int mi = q / NM2, ni = q % NM2;
        double beta = PI_D * (2 * b + 1) / 40.0;
        g_d12w[i] = (float)(g_w10[b] * wigd(l, mi - 5, ni - 5, beta));
    } else if (idx < O_Y1) {
        int i = idx - O_D2W;
        int l = i / (NB2 * NM2 * NM2); int r = i % (NB2 * NM2 * NM2);
        int b = r / (NM2 * NM2); int q = r % (NM2 * NM2);
        int mi = q / NM2, ni = q % NM2;
        double beta = PI_D * (2 * b + 1) / 24.0;
        g_d2w[i] = (float)((2 * l + 1) * wigd(l, mi - 5, ni - 5, beta));
    } else if (idx < O_D2) {
        int i = idx - O_Y1;
        int l = i / (24 * NM1); int r = i % (24 * NM1);
        int g = r / NM1, mi = r % NM1;
        int ib = g / 8, ja = g % 8;
        double beta = (ib + 1) * PI_D / 24.0;
        double alpha = 2.0 * PI_D * ja / 8.0;
        int m = mi - 9;
        double d = wigd(l, m, 0, beta);
        double th = -(double)m * alpha;
        g_Y1[i] = make_float2((float)(d * cos(th)), (float)(d * sin(th)));
    } else {
        int i = idx - O_D2;
        int l = i / (144 * NM2 * NM2); int r = i % (144 * NM2 * NM2);
        int g = r / (NM2 * NM2); int q = r % (NM2 * NM2);
        int mi = q / NM2, ni = q % NM2;
        int ib = g / 48, ja = (g / 6) % 8, kg = g % 6;
        double beta = (ib + 1) * PI_D / 24.0;
        double alpha = 2.0 * PI_D * ja / 8.0;
        double gamma = 2.0 * PI_D * kg / 6.0;
        int m = mi - 5, n = ni - 5;
        double d = wigd(l, m, n, beta);
        double th = -((double)m * alpha + (double)n * gamma);
        g_D2[i] = make_float2((float)(d * cos(th)), (float)(d * sin(th)));
    }
}

// ---------------- Psi1[l][o][ni] = sum_g psi1[o][g] * Y1[l][g][ni] ----------------
__global__ void k_psi1(const float* __restrict__ psi1) {
    int idx = blockIdx.x * blockDim.x + threadIdx.x;
    if (idx >= NL1 * NF1 * NM1) return;
    int l = idx / (NF1 * NM1);
    int o = (idx / NM1) % NF1;
    int mi = idx % NM1;
    float2 acc = make_float2(0.f, 0.f);
    for (int g = 0; g < 24; ++g) {
        float w = psi1[o * 24 + g];
        float2 y = g_Y1[(l * 24 + g) * NM1 + mi];
        acc.x += w * y.x; acc.y += w * y.y;
    }
    g_Psi1[(l * NF1 + o) * NM1 + mi] = acc;
}

// ---------------- E1[o][b][l][mi][g] = sum_ni d1w[l,b,mi,ni]*Psi1[l,o,ni]*e^{+i ni g} ----------------
__global__ void k_E1() {
    int idx = blockIdx.x * blockDim.x + threadIdx.x;
    if (idx >= NF1 * NB1 * NL1 * NM1 * 20) return;
    int g  = idx % 20;
    int mi = (idx / 20) % NM1;
    int l  = (idx / (20 * NM1)) % NL1;
    int b  = (idx / (20 * NM1 * NL1)) % NB1;
    int o  = idx / (20 * NM1 * NL1 * NB1);
    float2 acc = make_float2(0.f, 0.f);
    const float* dw = &g_d1w[((l * NB1 + b) * NM1 + mi) * NM1];
    const float2* ps = &g_Psi1[(l * NF1 + o) * NM1];
    for (int ni = 0; ni < NM1; ++ni) {
        float d = dw[ni];
        float2 p = ps[ni];
        float2 e = g_E20P[ni * 20 + g];
        float pr = p.x * e.x - p.y * e.y;
        float pi = p.x * e.y + p.y * e.x;
        acc.x += d * pr; acc.y += d * pi;
    }
    g_E1[idx] = acc;
}

// ---------------- B2[l][ik][on] = Psi2[l,i,o,k,n] = sum_g psi2[i,o,g]*D2[l,g,k,n] ----------------
__global__ void k_B2(const float* __restrict__ psi2) {
    int l = blockIdx.x / NM2;
    int ki = blockIdx.x % NM2;
    __shared__ float2 sD[144 * NM2]; // [g][ni]
    for (int t = threadIdx.x; t < 144 * NM2; t += blockDim.x) {
        int g = t / NM2, ni = t % NM2;
        sD[t] = g_D2[((l * 144 + g) * NM2 + ki) * NM2 + ni];
    }
    __syncthreads();
    for (int t = threadIdx.x; t < NF1 * NF2 * NM2; t += blockDim.x) {
        int i = t / (NF2 * NM2);
        int rem = t % (NF2 * NM2);
        int o = rem / NM2, ni = rem % NM2;
        float2 acc = make_float2(0.f, 0.f);
        const float* p = psi2 + (size_t)(i * NF2 + o) * 144;
        for (int g = 0; g < 144; ++g) {
            float w = p[g];
            float2 d = sD[g * NM2 + ni];
            acc.x += w * d.x; acc.y += w * d.y;
        }
        g_B2[((size_t)l * 220 + (i * NM2 + ki)) * 440 + (o * NM2 + ni)] = acc;
    }
}

// ---------------- X[z][l][mi] : azimuthal DFT + Legendre transform ----------------
__global__ void k_X(const float* __restrict__ x) {
    __shared__ float sx[3600];
    __shared__ float2 sxf[NB_IN * NM1]; // [b][mi]
    int z = blockIdx.x;
    for (int t = threadIdx.x; t < 3600; t += blockDim.x)
        sx[t] = x[(size_t)z * 3600 + t];
    __syncthreads();
    for (int t = threadIdx.x; t < NB_IN * NM1; t += blockDim.x) {
        int b = t / NM1, mi = t % NM1;
        float re = 0.f, im = 0.f;
        const float* row = &sx[b * 60];
        const float2* tw = &g_T60[mi * 60];
        for (int a = 0; a < 60; ++a) {
            float v = row[a];
            re += v * tw[a].x; im += v * tw[a].y;
        }
        sxf[t] = make_float2(re, im);
    }
    __syncthreads();
    for (int t = threadIdx.x; t < NL1 * NM1; t += blockDim.x) {
        int l = t / NM1, mi = t % NM1;
        float2 acc = make_float2(0.f, 0.f);
        for (int b = 0; b < NB_IN; ++b) {
            float w = g_wd_s2[(l * NB_IN + b) * NM1 + mi];
            float2 v = sxf[b * NM1 + mi];
            acc.x += w * v.x; acc.y += w * v.y;
        }
        g_X[z * (NL1 * NM1) + t] = acc; // [z][l][mi]
    }
}

// ---------------- S1[z][o][b][mi][g] = sum_l X[z,l,mi] * E1[o,b,l,mi,g] ----------------
__global__ void k_S1() {
    __shared__ float2 sE[NL1 * NM1 * 20]; // [l][mi][g] 3800
    __shared__ float2 sX[NL1 * NM1];      // [l][mi]
    int b = blockIdx.x, o = blockIdx.y, zc = blockIdx.z;
    const float2* e1 = &g_E1[(size_t)(o * NB1 + b) * (NL1 * NM1 * 20)];
    for (int t = threadIdx.x; t < NL1 * NM1 * 20; t += blockDim.x)
        sE[t] = e1[t];
    __syncthreads();
    for (int zz = 0; zz < 32; ++zz) {
        int z = zc * 32 + zz;
        for (int t = threadIdx.x; t < NL1 * NM1; t += blockDim.x)
            sX[t] = g_X[z * (NL1 * NM1) + t];
        __syncthreads();
        size_t base = ((size_t)((z * NF1 + o) * NB1 + b)) * (NM1 * 20);
        for (int t = threadIdx.x; t < NM1 * 20; t += blockDim.x) {
            int mi = t / 20, g = t % 20;
            float2 acc = make_float2(0.f, 0.f);
            #pragma unroll
            for (int l = 0; l < NL1; ++l) {
                float2 xv = sX[l * NM1 + mi];
                float2 ev = sE[(l * NM1 + mi) * 20 + g];
                acc.x += xv.x * ev.x - xv.y * ev.y;
                acc.y += xv.x * ev.y + xv.y * ev.x;
            }
            g_S1[base + t] = acc;
        }
        __syncthreads();
    }
}

// ---------------- fused: synth (ifft2+relu) + forward SO3 FFT gather -> Yg ----------------
__global__ void k_yYg() {
    __shared__ float2 sS[NM1 * 20];   // [mi][g]
    __shared__ float2 sEp[NM1 * 20];
    __shared__ float2 sEm[NM2 * 20];
    __shared__ float2 sA[NM2 * 20];   // Ya [mi2][g]
    __shared__ float  sY[400];        // [a][g]
    size_t zob = blockIdx.x;
    for (int t = threadIdx.x; t < NM1 * 20; t += blockDim.x) {
        sS[t] = g_S1[zob * (NM1 * 20) + t];
        sEp[t] = g_E20P[t];
    }
    for (int t = threadIdx.x; t < NM2 * 20; t += blockDim.x)
        sEm[t] = g_E20M[t];
    __syncthreads();
    for (int t = threadIdx.x; t < 400; t += blockDim.x) {
        int a = t / 20, g = t % 20;
        float v = 0.f;
        #pragma unroll
        for (int mi = 0; mi < NM1; ++mi) {
            float2 s = sS[mi * 20 + g];
            float2 e = sEp[mi * 20 + a];
            v += s.x * e.x - s.y * e.y;
        }
        sY[t] = fmaxf(v, 0.f);
    }
    __syncthreads();
    for (int t = threadIdx.x; t < NM2 * 20; t += blockDim.x) {
        int mi = t / 20, g = t % 20;
        float2 acc = make_float2(0.f, 0.f);
        #pragma unroll
        for (int a = 0; a < 20; ++a) {
            float yv = sY[a * 20 + g];
            float2 e = sEm[mi * 20 + a];
            acc.x += yv * e.x; acc.y += yv * e.y;
        }
        sA[t] = acc;
    }
    __syncthreads();
    for (int t = threadIdx.x; t < NM2 * NM2; t += blockDim.x) {
        int mi = t / NM2, ni = t % NM2;
        float2 acc = make_float2(0.f, 0.f);
        #pragma unroll
        for (int g = 0; g < 20; ++g)
            acc = make_float2(acc.x + sA[mi * 20 + g].x * sEm[ni * 20 + g].x - sA[mi * 20 + g].y * sEm[ni * 20 + g].y,
                              acc.y + sA[mi * 20 + g].x * sEm[ni * 20 + g].y + sA[mi * 20 + g].y * sEm[ni * 20 + g].x);
        g_Yg[zob * (NM2 * NM2) + t] = acc;
    }
}

// ---------------- Fx[(l,mi)][z][i*11+ki] = sum_b d12w[l,b,mi,ki]*Yg[z,i,b,mi,ki] ----------------
__global__ void k_Fx() {
    int z = blockIdx.x / NF1;
    int i = blockIdx.x % NF1;
    __shared__ float2 sYs[NB1 * NM2 * NM2]; // [b][mn] 2420
    size_t base = ((size_t)(z * NF1 + i)) * NB1 * (NM2 * NM2);
    for (int t = threadIdx.x; t < NB1 * NM2 * NM2; t += blockDim.x)
        sYs[t] = g_Yg[base + t];
    __syncthreads();
    for (int t = threadIdx.x; t < NL2 * NM2 * NM2; t += blockDim.x) {
        int l = t / (NM2 * NM2);
        int mn = t % (NM2 * NM2);
        int mi = mn / NM2, ki = mn % NM2;
        float2 acc = make_float2(0.f, 0.f);
        #pragma unroll
        for (int b = 0; b < NB1; ++b) {
            float d = g_d12w[(l * NB1 + b) * (NM2 * NM2) + mn];
            float2 v = sYs[b * (NM2 * NM2) + mn];
            acc.x += d * v.x; acc.y += d * v.y;
        }
        g_Fx[(((size_t)(l * NM2 + mi)) * BATCH + z) * 220 + (i * NM2 + ki)] = acc;
    }
}

// ---------------- Fo: 66 complex GEMMs  C[z,(o,n)] = sum_ik A[z,ik]*B[ik,(o,n)] ----------------
#define FO_ZT 16
__global__ void k_Fo() {
    int l = blockIdx.x / NM2;
    int mi = blockIdx.x % NM2;
    int z0 = blockIdx.y * FO_ZT;
    __shared__ float2 sAa[FO_ZT * 220];
    size_t abase = ((size_t)(l * NM2 + mi) * BATCH + z0) * 220;
    for (int t = threadIdx.x; t < FO_ZT * 220; t += blockDim.x)
        sAa[t] = g_Fx[abase + t];
    __syncthreads();
    for (int col = threadIdx.x; col < 440; col += blockDim.x) {
        float2 acc[FO_ZT];
        #pragma unroll
        for (int zz = 0; zz < FO_ZT; ++zz) acc[zz] = make_float2(0.f, 0.f);
        const float2* Bp = g_B2 + (size_t)l * 220 * 440 + col;
        for (int ik = 0; ik < 220; ++ik) {
            float2 bv = Bp[(size_t)ik * 440];
            #pragma unroll
            for (int zz = 0; zz < FO_ZT; ++zz) {
                float2 av = sAa[zz * 220 + ik];
                acc[zz].x += av.x * bv.x - av.y * bv.y;
                acc[zz].y += av.x * bv.y + av.y * bv.x;
            }
        }
        int o = col / NM2, ni = col % NM2;
        #pragma unroll
        for (int zz = 0; zz < FO_ZT; ++zz) {
            int z = z0 + zz;
            g_Fo[((size_t)(z * NF2 + o) * NL2 + l) * (NM2 * NM2) + mi * NM2 + ni] = acc[zz];
        }
    }
}

// ---------------- final: d2w contraction + ifft2(12x12) + relu + quadrature reduce ----------------
__global__ void k_final() {
    __shared__ float2 sFo[NL2 * NM2 * NM2];     // 726
    __shared__ float2 sFh2[NB2 * NM2 * NM2];    // 1452
    __shared__ float2 sS2[NB2 * NM2 * 12];      // 1584
    __shared__ float2 sE12[NM2 * 12];
    __shared__ float  sred[256];
    int zo = blockIdx.x;
    for (int t = threadIdx.x; t < NL2 * NM2 * NM2; t += blockDim.x)
        sFo[t] = g_Fo[(size_t)zo * (NL2 * NM2 * NM2) + t];
    for (int t = threadIdx.x; t < NM2 * 12; t += blockDim.x)
        sE12[t] = g_E12P[t];
    __syncthreads();
    for (int t = threadIdx.x; t < NB2 * NM2 * NM2; t += blockDim.x) {
        int b = t / (NM2 * NM2), mn = t % (NM2 * NM2);
        float2 acc = make_float2(0.f, 0.f);
        #pragma unroll
        for (int l = 0; l < NL2; ++l) {
            float d = g_d2w[(l * NB2 + b) * (NM2 * NM2) + mn];
            float2 f = sFo[l * (NM2 * NM2) + mn];
            acc.x += d * f.x; acc.y += d * f.y;
        }
        sFh2[t] = acc;
    }
    __syncthreads();
    for (int t = threadIdx.x; t < NB2 * NM2 * 12; t += blockDim.x) {
        int b = t / (NM2 * 12);
        int r = t % (NM2 * 12);
        int mi = r / 12, g = r % 12;
        float2 acc = make_float2(0.f, 0.f);
        #pragma unroll
        for (int ni = 0; ni < NM2; ++ni) {
            float2 f = sFh2[b * (NM2 * NM2) + mi * NM2 + ni];
            float2 e = sE12[ni * 12 + g];
            acc.x += f.x * e.x - f.y * e.y;
            acc.y += f.x * e.y + f.y * e.x;
        }
        sS2[t] = acc;
    }
    __syncthreads();
    float part = 0.f;
    for (int t = threadIdx.x; t < NB2 * 12 * 12; t += blockDim.x) {
        int b = t / 144;
        int r = t % 144;
        int a = r / 12, g = r % 12;
        float v = 0.f;
        #pragma unroll
        for (int mi = 0; mi < NM2; ++mi) {
            float2 s = sS2[(b * NM2 + mi) * 12 + g];
            float2 e = sE12[mi * 12 + a];
            v += s.x * e.x - s.y * e.y;
        }
        if (v > 0.f) part += g_w2n[b] * v;
    }
    sred[threadIdx.x] = part;
    __syncthreads();
    for (int s = 128; s > 0; s >>= 1) {
        if (threadIdx.x < s) sred[threadIdx.x] += sred[threadIdx.x + s];
        __syncthreads();
    }
    if (threadIdx.x == 0)
        g_feat[zo] = sred[0] * (1.0f / 144.0f);
}

// ---------------- linear head ----------------
__global__ void k_lin(const float* __restrict__ w_lin, const float* __restrict__ b_lin,
                      float* __restrict__ out) {
    int t = blockIdx.x * blockDim.x + threadIdx.x;
    if (t >= BATCH * 10) return;
    int z = t / 10, f = t % 10;
    float acc = b_lin[f];
    #pragma unroll
    for (int o = 0; o < NF2; ++o)
        acc += g_feat[z * NF2 + o] * w_lin[f * NF2 + o];
    out[t] = acc;
}

// ---------------- launch ----------------
extern "C" void kernel_launch(void* const* d_in, const int* in_sizes, int n_in,
                              void* d_out, int out_size) {
    const float* x     = (const float*)d_in[0];
    const float* psi1  = (const float*)d_in[1];
    const float* psi2  = (const float*)d_in[2];
    const float* w_lin = (const float*)d_in[3];
    const float* b_lin = (const float*)d_in[4];
    float* out = (float*)d_out;

    k_setup1<<<8, 256>>>();
    k_setup2<<<(N_SET2 + 255) / 256, 256>>>();
    k_psi1<<<(NL1 * NF1 * NM1 + 255) / 256, 256>>>(psi1);
    k_E1<<<(NF1 * NB1 * NL1 * NM1 * 20 + 255) / 256, 256>>>();
    k_B2<<<NL2 * NM2, 256>>>(psi2);
    k_X<<<BATCH, 256>>>(x);
    k_S1<<<dim3(NB1, NF1, 4), 256>>>();
    k_yYg<<<BATCH * NF1 * NB1, 256>>>();
    k_Fx<<<BATCH * NF1, 256>>>();
    k_Fo<<<dim3(NL2 * NM2, BATCH / FO_ZT), 256>>>();
    k_final<<<BATCH * NF2, 256>>>();
    k_lin<<<(BATCH * 10 + 255) / 256, 256>>>(w_lin, b_lin, out);
}

// round 2
// speedup vs baseline: 1.8658x; 1.8658x over previous
#include <cuda_runtime.h>
#include <cuda_bf16.h>
#include <math.h>

#define PI_D 3.14159265358979323846

#define BATCH 128
#define NB_IN 60
#define NM1 19
#define NL1 10
#define NF1 20
#define NB1 20
#define NM2 11
#define NL2 6
#define NF2 40
#define NB2 12

// ---------------- device tables ----------------
__device__ double g_lf[64];
__device__ double g_w30[60];
__device__ double g_w10[20];
__device__ float  g_w2n[12];

__device__ float2 g_T60[10 * 60];        // e^{-2pi i m a/60}, m=0..9
__device__ float2 g_E20P[19 * 20];       // e^{+2pi i (ni-9) x/20}
__device__ float2 g_E20M[11 * 20];       // e^{-2pi i (mi-5) x/20}
__device__ float2 g_E12P[11 * 12];       // e^{+2pi i (ni-5) x/12}

__device__ float  g_wd_s2[10 * 60 * 10];     // [l][b][m0..9]
__device__ float  g_d1w[10 * 20 * 10 * 19];  // [l][b][m0..9][ni]
__device__ float  g_d12w[6 * 20 * 6 * 11];   // [l][b][m0..5][ki]
__device__ float  g_d2w[6 * 12 * 6 * 11];    // [l][b][m0..5][ni]
__device__ float2 g_Y1[10 * 24 * 19];        // [l][g][ni]
__device__ float2 g_D2[6 * 144 * 11 * 11];   // [l][g][ki][ni]

__device__ float2 g_Psi1[10 * 20 * 19];          // [l][o][ni]
__device__ float2 g_E1[20 * 20 * 10 * 10 * 20];  // [o][b][l][m0..9][g]
__device__ float2 g_X[BATCH * 100];              // [z][l*10+m]
__device__ float2 g_Yg[(size_t)BATCH * 20 * 20 * 66]; // [z][c][b][m*11+ni]
__device__ float2 g_Fx[(size_t)128 * 3220];      // packed [p][z][ik]
__device__ __align__(16) float2 g_B2[316800];    // packed [l][ik][o*11+ni]
__device__ float2 g_Fo[(size_t)BATCH * NF2 * 21 * 11]; // [z][o][p][ni]
__device__ float  g_feat[BATCH * NF2];

// p = (l,m) valid pairs, m<=l<=5
__constant__ int cPl[21]   = {0,1,1,2,2,2,3,3,3,3,4,4,4,4,4,5,5,5,5,5,5};
__constant__ int cPm[21]   = {0,0,1,0,1,2,0,1,2,3,0,1,2,3,4,0,1,2,3,4,5};
__constant__ int cPref[21] = {0,20,80,140,240,340,440,580,720,860,1000,1180,1360,1540,1720,1900,2120,2340,2560,2780,3000};
__constant__ int cOutOff[22] = {0,1,4,7,12,17,22,29,36,43,50,59,68,77,86,95,106,117,128,139,150,161};
__constant__ int cBl[36]  = {0,1,1,1,2,2,2,2,2,3,3,3,3,3,3,3,4,4,4,4,4,4,4,4,4,5,5,5,5,5,5,5,5,5,5,5};
__constant__ int cBkk[36] = {0,0,1,2,0,1,2,3,4,0,1,2,3,4,5,6,0,1,2,3,4,5,6,7,8,0,1,2,3,4,5,6,7,8,9,10};

__device__ __forceinline__ double dpow_i(double x, int p) {
    double r = 1.0;
    for (int i = 0; i < p; ++i) r *= x;
    return r;
}

__device__ double wigd(int l, int m, int n, double beta) {
    if (m > l || m < -l || n > l || n < -l) return 0.0;
    double cb = cos(0.5 * beta), sb = sin(0.5 * beta);
    double pref = 0.5 * (g_lf[l + m] + g_lf[l - m] + g_lf[l + n] + g_lf[l - n]);
    int s0 = max(0, n - m), s1 = min(l + n, l - m);
    double acc = 0.0;
    for (int s = s0; s <= s1; ++s) {
        double c = pref - (g_lf[l + n - s] + g_lf[s] + g_lf[m - n + s] + g_lf[l - m - s]);
        double t = exp(c) * dpow_i(cb, 2 * l + n - m - 2 * s) * dpow_i(sb, m - n + 2 * s);
        acc += ((m - n + s) & 1) ? -t : t;
    }
    return acc;
}

__device__ double dh_w_val(int bsz, int k) {
    double beta = PI_D * (2 * k + 1) / (4.0 * bsz);
    double s = 0.0;
    for (int j = 0; j < bsz; ++j)
        s += sin((2 * j + 1) * beta) / (2 * j + 1);
    return (2.0 / bsz) * sin(beta) * s;
}

// ---------------- setup 1 ----------------
__global__ void k_setup1() {
    int idx = blockIdx.x * blockDim.x + threadIdx.x;
    if (idx < 600) { // T60, m=0..9
        int m = idx / 60, a = idx % 60;
        double th = -2.0 * PI_D * m * a / 60.0;
        g_T60[idx] = make_float2((float)cos(th), (float)sin(th));
    } else if (idx < 980) { // E20P
        int r = idx - 600; int ni = r / 20, x = r % 20;
        double th = 2.0 * PI_D * (ni - 9) * x / 20.0;
        g_E20P[r] = make_float2((float)cos(th), (float)sin(th));
    } else if (idx < 1200) { // E20M
        int r = idx - 980; int mi = r / 20, x = r % 20;
        double th = -2.0 * PI_D * (mi - 5) * x / 20.0;
        g_E20M[r] = make_float2((float)cos(th), (float)sin(th));
    } else if (idx < 1332) { // E12P
        int r = idx - 1200; int ni = r / 12, x = r % 12;
        double th = 2.0 * PI_D * (ni - 5) * x / 12.0;
        g_E12P[r] = make_float2((float)cos(th), (float)sin(th));
    } else if (idx < 1392) {
        g_w30[idx - 1332] = dh_w_val(30, idx - 1332);
    } else if (idx < 1412) {
        g_w10[idx - 1392] = dh_w_val(10, idx - 1392);
    } else if (idx < 1424) {
        int k = idx - 1412;
        double s = 0.0;
        for (int j = 0; j < 12; ++j) s += dh_w_val(6, j);
        g_w2n[k] = (float)(dh_w_val(6, k) / s);
    } else if (idx < 1465) {
        int n = idx - 1424;
        g_lf[n] = lgamma(n + 1.0);
    }
}

// ---------------- setup 2 ----------------
#define O_WDS2 0
#define N_WDS2 6000
#define O_D1W  6000
#define N_D1W  38000
#define O_D12W 44000
#define N_D12W 7920
#define O_D2W  51920
#define N_D2W  4752
#define O_Y1s  56672
#define N_Y1s  4560
#define O_D2s  61232
#define N_D2s  104544
#define N_SET2 165776

__global__ void k_setup2() {
    int idx = blockIdx.x * blockDim.x + threadIdx.x;
    if (idx >= N_SET2) return;
    if (idx < O_D1W) {
        int i = idx;
        int l = i / 600, b = (i % 600) / 10, m = i % 10;
        double beta = PI_D * (2 * b + 1) / 120.0;
        g_wd_s2[i] = (float)(g_w30[b] * wigd(l, m, 0, beta));
    } else if (idx < O_D12W) {
        int i = idx - O_D1W;
        int l = i / 3800; int r = i % 3800;
        int b = r / 190; int q = r % 190;
        int m = q / 19, ni = q % 19;
        double beta = PI_D * (2 * b + 1) / 40.0;
        g_d1w[i] = (float)((2 * l + 1) * wigd(l, m, ni - 9, beta));
    } else if (idx < O_D2W) {
        int i = idx - O_D12W;
        int l = i / 1320; int r = i % 1320;
        int b = r / 66; int q = r % 66;
        int m = q / 11, ki = q % 11;
        double beta = PI_D * (2 * b + 1) / 40.0;
        g_d12w[i] = (float)(g_w10[b] * wigd(l, m, ki - 5, beta));
    } else if (idx < O_Y1s) {
        int i = idx - O_D2W;
        int l = i / 792; int r = i % 792;
        int b = r / 66; int q = r % 66;
        int m = q / 11, ni = q % 11;
        double beta = PI_D * (2 * b + 1) / 24.0;
        g_d2w[i] = (float)((2 * l + 1) * wigd(l, m, ni - 5, beta));
    } else if (idx < O_D2s) {
        int i = idx - O_Y1s;
        int l = i / (24 * 19); int r = i % (24 * 19);
        int g = r / 19, mi = r % 19;
        int ib = g / 8, ja = g % 8;
        double beta = (ib + 1) * PI_D / 24.0;
        double alpha = 2.0 * PI_D * ja / 8.0;
        int m = mi - 9;
        double d = wigd(l, m, 0, beta);
        double th = -(double)m * alpha;
        g_Y1[i] = make_float2((float)(d * cos(th)), (float)(d * sin(th)));
    } else {
        int i = idx - O_D2s;
        int l = i / (144 * 121); int r = i % (144 * 121);
        int g = r / 121; int q = r % 121;
        int ki = q / 11, ni = q % 11;
        int ib = g / 48, ja = (g / 6) % 8, kg = g % 6;
        double beta = (ib + 1) * PI_D / 24.0;
        double alpha = 2.0 * PI_D * ja / 8.0;
        double gamma = 2.0 * PI_D * kg / 6.0;
        int m = ki - 5, n = ni - 5;
        double d = wigd(l, m, n, beta);
        double th = -((double)m * alpha + (double)n * gamma);
        g_D2[i] = make_float2((float)(d * cos(th)), (float)(d * sin(th)));
    }
}

// ---------------- Psi1 ----------------
__global__ void k_psi1(const float* __restrict__ psi1) {
    int idx = blockIdx.x * blockDim.x + threadIdx.x;
    if (idx >= 10 * 20 * 19) return;
    int l = idx / (20 * 19);
    int o = (idx / 19) % 20;
    int ni = idx % 19;
    float2 acc = make_float2(0.f, 0.f);
    for (int g = 0; g < 24; ++g) {
        float w = psi1[o * 24 + g];
        float2 y = g_Y1[(l * 24 + g) * 19 + ni];
        acc.x += w * y.x; acc.y += w * y.y;
    }
    g_Psi1[(l * 20 + o) * 19 + ni] = acc;
}

// ---------------- E1[o][b][l][m0..9][g] ----------------
__global__ void k_E1() {
    int idx = blockIdx.x * blockDim.x + threadIdx.x;
    if (idx >= 800000) return;
    int g = idx % 20;
    int m = (idx / 20) % 10;
    int l = (idx / 200) % 10;
    int b = (idx / 2000) % 20;
    int o = idx / 40000;
    float2 acc = make_float2(0.f, 0.f);
    const float* dw = &g_d1w[((l * 20 + b) * 10 + m) * 19];
    const float2* ps = &g_Psi1[(l * 20 + o) * 19];
    for (int ni = 0; ni < 19; ++ni) {
        float d = dw[ni];
        float2 p = ps[ni];
        float2 e = g_E20P[ni * 20 + g];
        acc.x += d * (p.x * e.x - p.y * e.y);
        acc.y += d * (p.x * e.y + p.y * e.x);
    }
    g_E1[idx] = acc;
}

// ---------------- B2 packed: [l][(i*(2l+1)+kk)][o*11+ni] ----------------
__global__ void k_B2(const float* __restrict__ psi2) {
    int blk = blockIdx.x;
    int l = cBl[blk], kk = cBkk[blk];
    int kidx = kk - l + 5;
    __shared__ float2 sD[144 * 11];
    for (int t = threadIdx.x; t < 144 * 11; t += blockDim.x) {
        int g = t / 11, ni = t % 11;
        sD[t] = g_D2[((l * 144 + g) * 11 + kidx) * 11 + ni];
    }
    __syncthreads();
    size_t boff = (size_t)8800 * l * l;
    for (int pr = threadIdx.x; pr < 800; pr += blockDim.x) {
        int i = pr / 40, o = pr % 40;
        float2 acc[11];
        #pragma unroll
        for (int ni = 0; ni < 11; ++ni) acc[ni] = make_float2(0.f, 0.f);
        const float* pp = psi2 + (size_t)pr * 144;
        for (int g = 0; g < 144; ++g) {
            float w = pp[g];
            const float2* dp = &sD[g * 11];
            #pragma unroll
            for (int ni = 0; ni < 11; ++ni) {
                acc[ni].x += w * dp[ni].x;
                acc[ni].y += w * dp[ni].y;
            }
        }
        size_t rb = boff + (size_t)(i * (2 * l + 1) + kk) * 440 + o * 11;
        #pragma unroll
        for (int ni = 0; ni < 11; ++ni) g_B2[rb + ni] = acc[ni];
    }
}

// ---------------- X[z][l*10+m], m=0..9 ----------------
__global__ void k_X(const float* __restrict__ x) {
    __shared__ float sx[3600];
    __shared__ float2 sxf[600]; // [b][m]
    int z = blockIdx.x;
    for (int t = threadIdx.x; t < 3600; t += blockDim.x)
        sx[t] = x[(size_t)z * 3600 + t];
    __syncthreads();
    for (int t = threadIdx.x; t < 600; t += blockDim.x) {
        int b = t / 10, m = t % 10;
        float re = 0.f, im = 0.f;
        const float* row = &sx[b * 60];
        const float2* tw = &g_T60[m * 60];
        for (int a = 0; a < 60; ++a) {
            float v = row[a];
            re += v * tw[a].x; im += v * tw[a].y;
        }
        sxf[t] = make_float2(re, im);
    }
    __syncthreads();
    for (int t = threadIdx.x; t < 100; t += blockDim.x) {
        int l = t / 10, m = t % 10;
        float2 acc = make_float2(0.f, 0.f);
        for (int b = 0; b < 60; ++b) {
            float w = g_wd_s2[(l * 60 + b) * 10 + m];
            float2 v = sxf[b * 10 + m];
            acc.x += w * v.x; acc.y += w * v.y;
        }
        g_X[z * 100 + t] = acc;
    }
}

// ---------------- fused mid: S1 -> synth+relu -> alpha/gamma analysis -> Yg ----------------
__global__ void k_mid() {
    __shared__ float2 sE1[2000];
    __shared__ float2 sTw1[200]; // [m0..9][a]
    __shared__ float2 sEm[220];  // [mi0..10][x]
    __shared__ float2 sX[400];   // [zz][l*10+m]
    __shared__ float2 sS[800];   // [zz][m*20+g]
    __shared__ float  sY[1600];  // [zz][a*20+g]
    __shared__ float2 sA[480];   // [zz][m2*20+g]
    int b = blockIdx.x, c = blockIdx.y;
    int tid = threadIdx.x;
    const float2* e1 = g_E1 + (size_t)(c * 20 + b) * 2000;
    for (int t = tid; t < 2000; t += 256) sE1[t] = e1[t];
    for (int t = tid; t < 200; t += 256) sTw1[t] = g_E20P[(t / 20 + 9) * 20 + t % 20];
    for (int t = tid; t < 220; t += 256) sEm[t] = g_E20M[t];
    __syncthreads();
    for (int zg = 0; zg < 32; ++zg) {
        int z0 = zg * 4;
        for (int t = tid; t < 400; t += 256)
            sX[t] = g_X[(z0 + t / 100) * 100 + t % 100];
        __syncthreads();
        // S1[m,g] = sum_l X[l,m] * E1[l,m,g]   (m = 0..9)
        for (int t = tid; t < 800; t += 256) {
            int zz = t / 200, r = t % 200;
            int m = r / 20, g = r % 20;
            float2 acc = make_float2(0.f, 0.f);
            const float2* xp = &sX[zz * 100 + m];
            const float2* ep = &sE1[m * 20 + g];
            #pragma unroll
            for (int l = 0; l < 10; ++l) {
                float2 xv = xp[l * 10];
                float2 ev = ep[l * 200];
                acc.x += xv.x * ev.x - xv.y * ev.y;
                acc.y += xv.x * ev.y + xv.y * ev.x;
            }
            sS[t] = acc;
        }
        __syncthreads();
        // y[a,g] = Re S1[0,g] + 2 sum_{m>0} Re(S1[m,g] e^{+ima}); relu
        for (int t = tid; t < 1600; t += 256) {
            int zz = t / 400, r = t % 400;
            int a = r / 20, g = r % 20;
            const float2* sp = &sS[zz * 200 + g];
            float v = sp[0].x;
            #pragma unroll
            for (int m = 1; m < 10; ++m) {
                float2 s = sp[m * 20];
                float2 e = sTw1[m * 20 + a];
                v += 2.f * (s.x * e.x - s.y * e.y);
            }
            sY[t] = fmaxf(v, 0.f);
        }
        __syncthreads();
        // A[m2,g] = sum_a y[a,g] e^{-i m2 a}   (m2 = 0..5)
        for (int t = tid; t < 480; t += 256) {
            int zz = t / 120, r = t % 120;
            int m2 = r / 20, g = r % 20;
            float2 acc = make_float2(0.f, 0.f);
            const float* yp = &sY[zz * 400 + g];
            const float2* ep = &sEm[(m2 + 5) * 20];
            #pragma unroll
            for (int a = 0; a < 20; ++a) {
                float yv = yp[a * 20];
                float2 e = ep[a];
                acc.x += yv * e.x; acc.y += yv * e.y;
            }
            sA[t] = acc;
        }
        __syncthreads();
        // Yg[m, n] = sum_g A[m,g] e^{-i n g}   (m=0..5, n=-5..5)
        for (int t = tid; t < 264; t += 256) {
            int zz = t / 66, r = t % 66;
            int m = r / 11, ni = r % 11;
            float2 acc = make_float2(0.f, 0.f);
            const float2* ap = &sA[zz * 120 + m * 20];
            const float2* ep = &sEm[ni * 20];
            #pragma unroll
            for (int g = 0; g < 20; ++g) {
                float2 av = ap[g], e = ep[g];
                acc.x += av.x * e.x - av.y * e.y;
                acc.y += av.x * e.y + av.y * e.x;
            }
            int z = z0 + zz;
            g_Yg[((size_t)((z * 20 + c) * 20 + b)) * 66 + r] = acc;
        }
        __syncthreads();
    }
}

// ---------------- Fx packed: [p][z][i*(2l+1)+kk] ----------------
__global__ void k_Fx() {
    __shared__ float2 sYs[1320]; // [b][m*11+ni]
    int zi = blockIdx.x;
    int z = zi / 20, i = zi % 20;
    for (int t = threadIdx.x; t < 1320; t += blockDim.x)
        sYs[t] = g_Yg[(size_t)zi * 1320 + t];
    __syncthreads();
    int t = threadIdx.x;
    if (t < 161) {
        int p = 0;
        while (t >= cOutOff[p + 1]) ++p;
        int kk = t - cOutOff[p];
        int l = cPl[p], m = cPm[p];
        int kidx = kk - l + 5;
        float2 acc = make_float2(0.f, 0.f);
        #pragma unroll
        for (int b = 0; b < 20; ++b) {
            float d = g_d12w[((l * 20 + b) * 6 + m) * 11 + kidx];
            float2 v = sYs[b * 66 + m * 11 + kidx];
            acc.x += d * v.x; acc.y += d * v.y;
        }
        int Kl = 20 * (2 * l + 1);
        g_Fx[(size_t)cPref[p] * 128 + (size_t)z * Kl + i * (2 * l + 1) + kk] = acc;
    }
}

// ---------------- Fo GEMM: 21 packed complex GEMMs ----------------
#define FO_ZT 8
__global__ void k_Fo() {
    __shared__ float2 sAa[FO_ZT * 220];
    int p = blockIdx.x;
    int z0 = blockIdx.y * FO_ZT;
    int l = cPl[p];
    int Kl = 20 * (2 * l + 1);
    size_t abase = (size_t)cPref[p] * 128 + (size_t)z0 * Kl;
    for (int t = threadIdx.x; t < FO_ZT * Kl; t += blockDim.x)
        sAa[t] = g_Fx[abase + t];
    __syncthreads();
    int t = threadIdx.x;
    if (t < 220) {
        int c0 = 2 * t, c1 = 2 * t + 1;
        float2 a0[FO_ZT], a1[FO_ZT];
        #pragma unroll
        for (int zz = 0; zz < FO_ZT; ++zz) { a0[zz] = make_float2(0.f, 0.f); a1[zz] = make_float2(0.f, 0.f); }
        const float4* Bp = (const float4*)(g_B2 + (size_t)8800 * l * l);
        for (int ik = 0; ik < Kl; ++ik) {
            float4 bb = Bp[ik * 220 + t];
            #pragma unroll
            for (int zz = 0; zz < FO_ZT; ++zz) {
                float2 av = sAa[zz * Kl + ik];
                a0[zz].x += av.x * bb.x - av.y * bb.y;
                a0[zz].y += av.x * bb.y + av.y * bb.x;
                a1[zz].x += av.x * bb.z - av.y * bb.w;
                a1[zz].y += av.x * bb.w + av.y * bb.z;
            }
        }
        int o0 = c0 / 11, n0 = c0 % 11;
        int o1 = c1 / 11, n1 = c1 % 11;
        #pragma unroll
        for (int zz = 0; zz < FO_ZT; ++zz) {
            int z = z0 + zz;
            g_Fo[((size_t)(z * 40 + o0) * 21 + p) * 11 + n0] = a0[zz];
            g_Fo[((size_t)(z * 40 + o1) * 21 + p) * 11 + n1] = a1[zz];
        }
    }
}

// ---------------- final: d2w + 12x12 synth (Hermitian) + relu + reduce ----------------
__global__ void k_final() {
    __shared__ float2 sFo[231];
    __shared__ float2 sE12[132];
    __shared__ float2 sFh2[792]; // [(b*6+m)*11+ni]
    __shared__ float2 sU[864];   // [(b*6+m)*12+g]
    __shared__ float  sw2[12];
    __shared__ float  sred[128];
    int zo = blockIdx.x;
    int tid = threadIdx.x;
    for (int t = tid; t < 231; t += 128) sFo[t] = g_Fo[(size_t)zo * 231 + t];
    for (int t = tid; t < 132; t += 128) sE12[t] = g_E12P[t];
    if (tid < 12) sw2[tid] = g_w2n[tid];
    __syncthreads();
    for (int t = tid; t < 792; t += 128) {
        int b = t / 66, r = t % 66;
        int m = r / 11, ni = r % 11;
        float2 acc = make_float2(0.f, 0.f);
        for (int l = m; l < 6; ++l) {
            float d = g_d2w[((l * 12 + b) * 6 + m) * 11 + ni];
            float2 f = sFo[(l * (l + 1) / 2 + m) * 11 + ni];
            acc.x += d * f.x; acc.y += d * f.y;
        }
        sFh2[(b * 6 + m) * 11 + ni] = acc;
    }
    __syncthreads();
    for (int t = tid; t < 864; t += 128) {
        int bm = t / 12, g = t % 12;
        float2 acc = make_float2(0.f, 0.f);
        const float2* fp = &sFh2[bm * 11];
        #pragma unroll
        for (int ni = 0; ni < 11; ++ni) {
            float2 f = fp[ni];
            float2 e = sE12[ni * 12 + g];
            acc.x += f.x * e.x - f.y * e.y;
            acc.y += f.x * e.y + f.y * e.x;
        }
        sU[bm * 12 + g] = acc;
    }
    __syncthreads();
    float part = 0.f;
    for (int t = tid; t < 1728; t += 128) {
        int bq = t / 144, r = t % 144;
        int a = r / 12, g = r % 12;
        const float2* up = &sU[bq * 72 + g];
        float v = up[0].x;
        #pragma unroll
        for (int m = 1; m < 6; ++m) {
            float2 u = up[m * 12];
            float2 e = sE12[(m + 5) * 12 + a];
            v += 2.f * (u.x * e.x - u.y * e.y);
        }
        if (v > 0.f) part += sw2[bq] * v;
    }
    sred[tid] = part;
    __syncthreads();
    for (int s = 64; s > 0; s >>= 1) {
        if (tid < s) sred[tid] += sred[tid + s];
        __syncthreads();
    }
    if (tid == 0) g_feat[zo] = sred[0] * (1.0f / 144.0f);
}

// ---------------- linear head ----------------
__global__ void k_lin(const float* __restrict__ w_lin, const float* __restrict__ b_lin,
                      float* __restrict__ out) {
    int t = blockIdx.x * blockDim.x + threadIdx.x;
    if (t >= BATCH * 10) return;
    int z = t / 10, f = t % 10;
    float acc = b_lin[f];
    #pragma unroll
    for (int o = 0; o < NF2; ++o)
        acc += g_feat[z * NF2 + o] * w_lin[f * NF2 + o];
    out[t] = acc;
}

// ---------------- launch ----------------
extern "C" void kernel_launch(void* const* d_in, const int* in_sizes, int n_in,
                              void* d_out, int out_size) {
    const float* x     = (const float*)d_in[0];
    const float* psi1  = (const float*)d_in[1];
    const float* psi2  = (const float*)d_in[2];
    const float* w_lin = (const float*)d_in[3];
    const float* b_lin = (const float*)d_in[4];
    float* out = (float*)d_out;

    k_setup1<<<6, 256>>>();
    k_setup2<<<(N_SET2 + 255) / 256, 256>>>();
    k_psi1<<<(10 * 20 * 19 + 255) / 256, 256>>>(psi1);
    k_E1<<<(800000 + 255) / 256, 256>>>();
    k_B2<<<36, 256>>>(psi2);
    k_X<<<BATCH, 256>>>(x);
    k_mid<<<dim3(20, 20), 256>>>();
    k_Fx<<<BATCH * 20, 256>>>();
    k_Fo<<<dim3(21, BATCH / FO_ZT), 256>>>();
    k_final<<<BATCH * NF2, 128>>>();
    k_lin<<<(BATCH * 10 + 255) / 256, 256>>>(w_lin, b_lin, out);
}

// round 3
// speedup vs baseline: 2.3350x; 1.2515x over previous
#include <cuda_runtime.h>
#include <cuda_bf16.h>
#include <math.h>

#define PI_D 3.14159265358979323846

#define BATCH 128
#define NF2 40

// ---------------- device tables ----------------
__device__ double g_lf[64];
__device__ double g_w30[60];
__device__ double g_w10[20];
__device__ float  g_w2n[12];

__device__ float2 g_T60[10 * 60];        // e^{-2pi i m a/60}, m=0..9
__device__ float2 g_E20P[19 * 20];       // e^{+2pi i (ni-9) x/20}
__device__ float2 g_E20M[11 * 20];       // e^{-2pi i (mi-5) x/20}
__device__ float2 g_E12P[11 * 12];       // e^{+2pi i (ni-5) x/12}

__device__ float  g_wd_s2[10 * 60 * 10];     // [l][b][m]
__device__ float  g_d1w[10 * 20 * 10 * 19];  // [l][b][m][ni]
__device__ float  g_d12w[6 * 20 * 6 * 11];   // [l][b][m][ki]
__device__ float  g_d2w[6 * 12 * 6 * 11];    // [l][b][m][ni]
__device__ float2 g_Y1[10 * 24 * 19];        // [l][g][ni]
__device__ float2 g_D2[6 * 144 * 11 * 11];   // [l][g][ki][ni]

__device__ __align__(16) float2 g_E1[20 * 20 * 2000]; // [o][b][(m*20+g)*10+l]
__device__ __align__(16) float2 g_X[BATCH * 100];     // [z][m*10+l]
__device__ float2 g_Yg[(size_t)BATCH * 20 * 20 * 66]; // [z][c][b][m*11+ni]
__device__ float2 g_Fx[(size_t)128 * 3220];           // packed [p][z][ik]
__device__ __align__(16) float2 g_B2[316800];         // packed [l][ik][o*11+ni]
__device__ float2 g_Fo[(size_t)BATCH * NF2 * 21 * 11];// [z][o][p][ni]
__device__ float  g_feat[BATCH * NF2];

// p = (l,m) valid pairs, m<=l<=5
__constant__ int cPl[21]   = {0,1,1,2,2,2,3,3,3,3,4,4,4,4,4,5,5,5,5,5,5};
__constant__ int cPm[21]   = {0,0,1,0,1,2,0,1,2,3,0,1,2,3,4,0,1,2,3,4,5};
__constant__ int cPref[21] = {0,20,80,140,240,340,440,580,720,860,1000,1180,1360,1540,1720,1900,2120,2340,2560,2780,3000};
__constant__ int cOutOff[22] = {0,1,4,7,12,17,22,29,36,43,50,59,68,77,86,95,106,117,128,139,150,161};
__constant__ int cBl[36]  = {0,1,1,1,2,2,2,2,2,3,3,3,3,3,3,3,4,4,4,4,4,4,4,4,4,5,5,5,5,5,5,5,5,5,5,5};
__constant__ int cBkk[36] = {0,0,1,2,0,1,2,3,4,0,1,2,3,4,5,6,0,1,2,3,4,5,6,7,8,0,1,2,3,4,5,6,7,8,9,10};

__device__ __forceinline__ float fpow_i(float x, int p) {
    float r = 1.f;
    for (int i = 0; i < p; ++i) r *= x;
    return r;
}

__device__ float wigf(int l, int m, int n, double beta) {
    if (m > l || m < -l || n > l || n < -l) return 0.f;
    float cb = (float)cos(0.5 * beta), sb = (float)sin(0.5 * beta);
    float pref = (float)(0.5 * (g_lf[l + m] + g_lf[l - m] + g_lf[l + n] + g_lf[l - n]));
    int s0 = max(0, n - m), s1 = min(l + n, l - m);
    float acc = 0.f;
    for (int s = s0; s <= s1; ++s) {
        float c = pref - (float)(g_lf[l + n - s] + g_lf[s] + g_lf[m - n + s] + g_lf[l - m - s]);
        float t = expf(c) * fpow_i(cb, 2 * l + n - m - 2 * s) * fpow_i(sb, m - n + 2 * s);
        acc += ((m - n + s) & 1) ? -t : t;
    }
    return acc;
}

__device__ double dh_w_val(int bsz, int k) {
    double beta = PI_D * (2 * k + 1) / (4.0 * bsz);
    double s = 0.0;
    for (int j = 0; j < bsz; ++j)
        s += sin((2 * j + 1) * beta) / (2 * j + 1);
    return (2.0 / bsz) * sin(beta) * s;
}

// ---------------- setup 1 ----------------
__global__ void k_setup1() {
    int idx = blockIdx.x * blockDim.x + threadIdx.x;
    if (idx < 600) {
        int m = idx / 60, a = idx % 60;
        double th = -2.0 * PI_D * m * a / 60.0;
        g_T60[idx] = make_float2((float)cos(th), (float)sin(th));
    } else if (idx < 980) {
        int r = idx - 600; int ni = r / 20, x = r % 20;
        double th = 2.0 * PI_D * (ni - 9) * x / 20.0;
        g_E20P[r] = make_float2((float)cos(th), (float)sin(th));
    } else if (idx < 1200) {
        int r = idx - 980; int mi = r / 20, x = r % 20;
        double th = -2.0 * PI_D * (mi - 5) * x / 20.0;
        g_E20M[r] = make_float2((float)cos(th), (float)sin(th));
    } else if (idx < 1332) {
        int r = idx - 1200; int ni = r / 12, x = r % 12;
        double th = 2.0 * PI_D * (ni - 5) * x / 12.0;
        g_E12P[r] = make_float2((float)cos(th), (float)sin(th));
    } else if (idx < 1392) {
        g_w30[idx - 1332] = dh_w_val(30, idx - 1332);
    } else if (idx < 1412) {
        g_w10[idx - 1392] = dh_w_val(10, idx - 1392);
    } else if (idx < 1424) {
        int k = idx - 1412;
        double s = 0.0;
        for (int j = 0; j < 12; ++j) s += dh_w_val(6, j);
        g_w2n[k] = (float)(dh_w_val(6, k) / s);
    } else if (idx < 1465) {
        int n = idx - 1424;
        g_lf[n] = lgamma(n + 1.0);
    }
}

// ---------------- setup 2 ----------------
#define O_D1W  6000
#define O_D12W 44000
#define O_D2W  51920
#define O_Y1s  56672
#define O_D2s  61232
#define N_SET2 165776

__global__ void k_setup2() {
    int idx = blockIdx.x * blockDim.x + threadIdx.x;
    if (idx >= N_SET2) return;
    if (idx < O_D1W) {
        int i = idx;
        int l = i / 600, b = (i % 600) / 10, m = i % 10;
        double beta = PI_D * (2 * b + 1) / 120.0;
        g_wd_s2[i] = (float)g_w30[b] * wigf(l, m, 0, beta);
    } else if (idx < O_D12W) {
        int i = idx - O_D1W;
        int l = i / 3800; int r = i % 3800;
        int b = r / 190; int q = r % 190;
        int m = q / 19, ni = q % 19;
        double beta = PI_D * (2 * b + 1) / 40.0;
        g_d1w[i] = (2 * l + 1) * wigf(l, m, ni - 9, beta);
    } else if (idx < O_D2W) {
        int i = idx - O_D12W;
        int l = i / 1320; int r = i % 1320;
        int b = r / 66; int q = r % 66;
        int m = q / 11, ki = q % 11;
        double beta = PI_D * (2 * b + 1) / 40.0;
        g_d12w[i] = (float)g_w10[b] * wigf(l, m, ki - 5, beta);
    } else if (idx < O_Y1s) {
        int i = idx - O_D2W;
        int l = i / 792; int r = i % 792;
        int b = r / 66; int q = r % 66;
        int m = q / 11, ni = q % 11;
        double beta = PI_D * (2 * b + 1) / 24.0;
        g_d2w[i] = (2 * l + 1) * wigf(l, m, ni - 5, beta);
    } else if (idx < O_D2s) {
        int i = idx - O_Y1s;
        int l = i / (24 * 19); int r = i % (24 * 19);
        int g = r / 19, mi = r % 19;
        int ib = g / 8, ja = g % 8;
        double beta = (ib + 1) * PI_D / 24.0;
        double alpha = 2.0 * PI_D * ja / 8.0;
        int m = mi - 9;
        float d = wigf(l, m, 0, beta);
        double th = -(double)m * alpha;
        g_Y1[i] = make_float2(d * (float)cos(th), d * (float)sin(th));
    } else {
        int i = idx - O_D2s;
        int l = i / (144 * 121); int r = i % (144 * 121);
        int g = r / 121; int q = r % 121;
        int ki = q / 11, ni = q % 11;
        int ib = g / 48, ja = (g / 6) % 8, kg = g % 6;
        double beta = (ib + 1) * PI_D / 24.0;
        double alpha = 2.0 * PI_D * ja / 8.0;
        double gamma = 2.0 * PI_D * kg / 6.0;
        int m = ki - 5, n = ni - 5;
        float d = wigf(l, m, n, beta);
        double th = -((double)m * alpha + (double)n * gamma);
        g_D2[i] = make_float2(d * (float)cos(th), d * (float)sin(th));
    }
}

// ---------------- E1 (psi1 folded in): grid (b=20, o=20) ----------------
__global__ void k_E1(const float* __restrict__ psi1) {
    __shared__ float2 sPsi[190];     // [l][ni]
    __shared__ float  sd1w[1900];    // [l][m][ni]
    __shared__ float2 sE20P[380];    // [ni][g]
    int b = blockIdx.x, o = blockIdx.y;
    int tid = threadIdx.x;
    for (int t = tid; t < 190; t += 256) {
        int l = t / 19, ni = t % 19;
        float2 acc = make_float2(0.f, 0.f);
        for (int g = 0; g < 24; ++g) {
            float w = psi1[o * 24 + g];
            float2 y = g_Y1[(l * 24 + g) * 19 + ni];
            acc.x += w * y.x; acc.y += w * y.y;
        }
        sPsi[t] = acc;
    }
    for (int t = tid; t < 1900; t += 256) {
        int l = t / 190, m = (t / 19) % 10, ni = t % 19;
        sd1w[t] = g_d1w[((l * 20 + b) * 10 + m) * 19 + ni];
    }
    for (int t = tid; t < 380; t += 256) sE20P[t] = g_E20P[t];
    __syncthreads();
    for (int t = tid; t < 2000; t += 256) {
        int l = t % 10;
        int g = (t / 10) % 20;
        int m = t / 200;
        float2 acc = make_float2(0.f, 0.f);
        const float* dw = &sd1w[(l * 10 + m) * 19];
        const float2* ps = &sPsi[l * 19];
        for (int ni = 0; ni < 19; ++ni) {
            float d = dw[ni];
            float2 p = ps[ni];
            float2 e = sE20P[ni * 20 + g];
            acc.x += d * (p.x * e.x - p.y * e.y);
            acc.y += d * (p.x * e.y + p.y * e.x);
        }
        g_E1[(size_t)(o * 20 + b) * 2000 + t] = acc;
    }
}

// ---------------- B2 packed ----------------
__global__ void k_B2(const float* __restrict__ psi2) {
    int blk = blockIdx.x;
    int l = cBl[blk], kk = cBkk[blk];
    int kidx = kk - l + 5;
    __shared__ float2 sD[144 * 11];
    for (int t = threadIdx.x; t < 144 * 11; t += blockDim.x) {
        int g = t / 11, ni = t % 11;
        sD[t] = g_D2[((l * 144 + g) * 11 + kidx) * 11 + ni];
    }
    __syncthreads();
    size_t boff = (size_t)8800 * l * l;
    for (int pr = threadIdx.x; pr < 800; pr += blockDim.x) {
        int i = pr / 40, o = pr % 40;
        float2 acc[11];
        #pragma unroll
        for (int ni = 0; ni < 11; ++ni) acc[ni] = make_float2(0.f, 0.f);
        const float* pp = psi2 + (size_t)pr * 144;
        for (int g = 0; g < 144; ++g) {
            float w = pp[g];
            const float2* dp = &sD[g * 11];
            #pragma unroll
            for (int ni = 0; ni < 11; ++ni) {
                acc[ni].x += w * dp[ni].x;
                acc[ni].y += w * dp[ni].y;
            }
        }
        size_t rb = boff + (size_t)(i * (2 * l + 1) + kk) * 440 + o * 11;
        #pragma unroll
        for (int ni = 0; ni < 11; ++ni) g_B2[rb + ni] = acc[ni];
    }
}

// ---------------- X[z][m*10+l] ----------------
__global__ void k_X(const float* __restrict__ x) {
    __shared__ float sx[3600];
    __shared__ float2 sxf[600]; // [b][m]
    int z = blockIdx.x;
    for (int t = threadIdx.x; t < 3600; t += blockDim.x)
        sx[t] = x[(size_t)z * 3600 + t];
    __syncthreads();
    for (int t = threadIdx.x; t < 600; t += blockDim.x) {
        int b = t / 10, m = t % 10;
        float re = 0.f, im = 0.f;
        const float* row = &sx[b * 60];
        const float2* tw = &g_T60[m * 60];
        for (int a = 0; a < 60; ++a) {
            float v = row[a];
            re += v * tw[a].x; im += v * tw[a].y;
        }
        sxf[t] = make_float2(re, im);
    }
    __syncthreads();
    for (int t = threadIdx.x; t < 100; t += blockDim.x) {
        int l = t / 10, m = t % 10;
        float2 acc = make_float2(0.f, 0.f);
        for (int b = 0; b < 60; ++b) {
            float w = g_wd_s2[(l * 60 + b) * 10 + m];
            float2 v = sxf[b * 10 + m];
            acc.x += w * v.x; acc.y += w * v.y;
        }
        g_X[z * 100 + m * 10 + l] = acc; // [z][m][l]
    }
}

// ---------------- fused mid: register-resident S1 -> y -> A, then Yg ----------------
__global__ __launch_bounds__(320) void k_mid() {
    __shared__ __align__(16) float2 sE1[2000]; // [m][g][l]
    __shared__ float2 sTw1[200];               // [m][a]
    __shared__ float2 sEm[220];                // [mi][x]
    __shared__ __align__(16) float2 sX[1600];  // [zz][m*10+l]
    __shared__ float2 sA[1920];                // [zz][m2*20+g]
    int b = blockIdx.x, c = blockIdx.y;
    int tid = threadIdx.x;
    const float2* e1 = g_E1 + (size_t)(c * 20 + b) * 2000;
    for (int t = tid; t < 2000; t += 320) sE1[t] = e1[t];
    for (int t = tid; t < 200; t += 320) sTw1[t] = g_E20P[(t / 20 + 9) * 20 + t % 20];
    for (int t = tid; t < 220; t += 320) sEm[t] = g_E20M[t];
    __syncthreads();
    int zz = tid / 20, g = tid % 20;
    for (int stage = 0; stage < 8; ++stage) {
        int z0 = stage * 16;
        for (int t = tid; t < 1600; t += 320)
            sX[t] = g_X[(z0 + t / 100) * 100 + t % 100];
        __syncthreads();
        // S1[m] = sum_l X[m,l] * E1[m,g,l]  (registers)
        float2 S1m[10];
        #pragma unroll
        for (int m = 0; m < 10; ++m) {
            const float4* xp = (const float4*)&sX[zz * 100 + m * 10];
            const float4* ep = (const float4*)&sE1[(m * 20 + g) * 10];
            float ar = 0.f, ai = 0.f;
            #pragma unroll
            for (int i = 0; i < 5; ++i) {
                float4 xv = xp[i];
                float4 ev = ep[i];
                ar += xv.x * ev.x - xv.y * ev.y;
                ai += xv.x * ev.y + xv.y * ev.x;
                ar += xv.z * ev.z - xv.w * ev.w;
                ai += xv.z * ev.w + xv.w * ev.z;
            }
            S1m[m] = make_float2(ar, ai);
        }
        // y[a] = Re S1[0] + 2 sum_m Re(S1[m] e^{ima}); relu (registers)
        float yv[20];
        #pragma unroll
        for (int a = 0; a < 20; ++a) {
            float v = S1m[0].x;
            #pragma unroll
            for (int m = 1; m < 10; ++m) {
                float2 e = sTw1[m * 20 + a];
                v += 2.f * (S1m[m].x * e.x - S1m[m].y * e.y);
            }
            yv[a] = fmaxf(v, 0.f);
        }
        // A[m2] = sum_a y[a] e^{-i m2 a} -> shared
        #pragma unroll
        for (int m2 = 0; m2 < 6; ++m2) {
            const float2* ep = &sEm[(m2 + 5) * 20];
            float ar = 0.f, ai = 0.f;
            #pragma unroll
            for (int a = 0; a < 20; ++a) {
                ar += yv[a] * ep[a].x;
                ai += yv[a] * ep[a].y;
            }
            sA[zz * 120 + m2 * 20 + g] = make_float2(ar, ai);
        }
        __syncthreads();
        // Yg[m,n] = sum_g A[m,g] e^{-i n g}
        for (int t = tid; t < 1056; t += 320) {
            int zz2 = t / 66, r = t % 66;
            int m = r / 11, ni = r % 11;
            float2 acc = make_float2(0.f, 0.f);
            const float2* ap = &sA[zz2 * 120 + m * 20];
            const float2* ep = &sEm[ni * 20];
            #pragma unroll
            for (int gg = 0; gg < 20; ++gg) {
                float2 av = ap[gg], e = ep[gg];
                acc.x += av.x * e.x - av.y * e.y;
                acc.y += av.x * e.y + av.y * e.x;
            }
            int z = z0 + zz2;
            g_Yg[((size_t)((z * 20 + c) * 20 + b)) * 66 + r] = acc;
        }
        __syncthreads();
    }
}

// ---------------- Fx packed ----------------
__global__ void k_Fx() {
    __shared__ float2 sYs[1320]; // [b][m*11+ni]
    int zi = blockIdx.x;
    int z = zi / 20, i = zi % 20;
    for (int t = threadIdx.x; t < 1320; t += blockDim.x)
        sYs[t] = g_Yg[(size_t)zi * 1320 + t];
    __syncthreads();
    int t = threadIdx.x;
    if (t < 161) {
        int p = 0;
        while (t >= cOutOff[p + 1]) ++p;
        int kk = t - cOutOff[p];
        int l = cPl[p], m = cPm[p];
        int kidx = kk - l + 5;
        float2 acc = make_float2(0.f, 0.f);
        #pragma unroll
        for (int b = 0; b < 20; ++b) {
            float d = g_d12w[((l * 20 + b) * 6 + m) * 11 + kidx];
            float2 v = sYs[b * 66 + m * 11 + kidx];
            acc.x += d * v.x; acc.y += d * v.y;
        }
        int Kl = 20 * (2 * l + 1);
        g_Fx[(size_t)cPref[p] * 128 + (size_t)z * Kl + i * (2 * l + 1) + kk] = acc;
    }
}

// ---------------- Fo GEMM (heavy-l first) ----------------
#define FO_ZT 8
__global__ void k_Fo() {
    __shared__ float2 sAa[FO_ZT * 220];
    int p = 20 - blockIdx.x;           // heavy (l=5) blocks first
    int z0 = blockIdx.y * FO_ZT;
    int l = cPl[p];
    int Kl = 20 * (2 * l + 1);
    size_t abase = (size_t)cPref[p] * 128 + (size_t)z0 * Kl;
    for (int t = threadIdx.x; t < FO_ZT * Kl; t += blockDim.x)
        sAa[t] = g_Fx[abase + t];
    __syncthreads();
    int t = threadIdx.x;
    if (t < 220) {
        float2 a0[FO_ZT], a1[FO_ZT];
        #pragma unroll
        for (int zz = 0; zz < FO_ZT; ++zz) { a0[zz] = make_float2(0.f, 0.f); a1[zz] = make_float2(0.f, 0.f); }
        const float4* Bp = (const float4*)(g_B2 + (size_t)8800 * l * l);
        for (int ik = 0; ik < Kl; ++ik) {
            float4 bb = Bp[ik * 220 + t];
            #pragma unroll
            for (int zz = 0; zz < FO_ZT; ++zz) {
                float2 av = sAa[zz * Kl + ik];
                a0[zz].x += av.x * bb.x - av.y * bb.y;
                a0[zz].y += av.x * bb.y + av.y * bb.x;
                a1[zz].x += av.x * bb.z - av.y * bb.w;
                a1[zz].y += av.x * bb.w + av.y * bb.z;
            }
        }
        int o0 = (2 * t) / 11, n0 = (2 * t) % 11;
        int o1 = (2 * t + 1) / 11, n1 = (2 * t + 1) % 11;
        #pragma unroll
        for (int zz = 0; zz < FO_ZT; ++zz) {
            int z = z0 + zz;
            g_Fo[((size_t)(z * 40 + o0) * 21 + p) * 11 + n0] = a0[zz];
            g_Fo[((size_t)(z * 40 + o1) * 21 + p) * 11 + n1] = a1[zz];
        }
    }
}

// ---------------- final ----------------
__global__ void k_final() {
    __shared__ float2 sFo[231];
    __shared__ float2 sE12[132];
    __shared__ float2 sFh2[792];
    __shared__ float2 sU[864];
    __shared__ float  sw2[12];
    __shared__ float  sred[128];
    int zo = blockIdx.x;
    int tid = threadIdx.x;
    for (int t = tid; t < 231; t += 128) sFo[t] = g_Fo[(size_t)zo * 231 + t];
    for (int t = tid; t < 132; t += 128) sE12[t] = g_E12P[t];
    if (tid < 12) sw2[tid] = g_w2n[tid];
    __syncthreads();
    for (int t = tid; t < 792; t += 128) {
        int b = t / 66, r = t % 66;
        int m = r / 11, ni = r % 11;
        float2 acc = make_float2(0.f, 0.f);
        for (int l = m; l < 6; ++l) {
            float d = g_d2w[((l * 12 + b) * 6 + m) * 11 + ni];
            float2 f = sFo[(l * (l + 1) / 2 + m) * 11 + ni];
            acc.x += d * f.x; acc.y += d * f.y;
        }
        sFh2[(b * 6 + m) * 11 + ni] = acc;
    }
    __syncthreads();
    for (int t = tid; t < 864; t += 128) {
        int bm = t / 12, g = t % 12;
        float2 acc = make_float2(0.f, 0.f);
        const float2* fp = &sFh2[bm * 11];
        #pragma unroll
        for (int ni = 0; ni < 11; ++ni) {
            float2 f = fp[ni];
            float2 e = sE12[ni * 12 + g];
            acc.x += f.x * e.x - f.y * e.y;
            acc.y += f.x * e.y + f.y * e.x;
        }
        sU[bm * 12 + g] = acc;
    }
    __syncthreads();
    float part = 0.f;
    for (int t = tid; t < 1728; t += 128) {
        int bq = t / 144, r = t % 144;
        int a = r / 12, g = r % 12;
        const float2* up = &sU[bq * 72 + g];
        float v = up[0].x;
        #pragma unroll
        for (int m = 1; m < 6; ++m) {
            float2 u = up[m * 12];
            float2 e = sE12[(m + 5) * 12 + a];
            v += 2.f * (u.x * e.x - u.y * e.y);
        }
        if (v > 0.f) part += sw2[bq] * v;
    }
    sred[tid] = part;
    __syncthreads();
    for (int s = 64; s > 0; s >>= 1) {
        if (tid < s) sred[tid] += sred[tid + s];
        __syncthreads();
    }
    if (tid == 0) g_feat[zo] = sred[0] * (1.0f / 144.0f);
}

// ---------------- linear head ----------------
__global__ void k_lin(const float* __restrict__ w_lin, const float* __restrict__ b_lin,
                      float* __restrict__ out) {
    int t = blockIdx.x * blockDim.x + threadIdx.x;
    if (t >= BATCH * 10) return;
    int z = t / 10, f = t % 10;
    float acc = b_lin[f];
    #pragma unroll
    for (int o = 0; o < NF2; ++o)
        acc += g_feat[z * NF2 + o] * w_lin[f * NF2 + o];
    out[t] = acc;
}

// ---------------- launch ----------------
extern "C" void kernel_launch(void* const* d_in, const int* in_sizes, int n_in,
                              void* d_out, int out_size) {
    const float* x     = (const float*)d_in[0];
    const float* psi1  = (const float*)d_in[1];
    const float* psi2  = (const float*)d_in[2];
    const float* w_lin = (const float*)d_in[3];
    const float* b_lin = (const float*)d_in[4];
    float* out = (float*)d_out;

    k_setup1<<<6, 256>>>();
    k_setup2<<<(N_SET2 + 255) / 256, 256>>>();
    k_E1<<<dim3(20, 20), 256>>>(psi1);
    k_B2<<<36, 256>>>(psi2);
    k_X<<<BATCH, 256>>>(x);
    k_mid<<<dim3(20, 20), 320>>>();
    k_Fx<<<BATCH * 20, 192>>>();
    k_Fo<<<dim3(21, BATCH / FO_ZT), 256>>>();
    k_final<<<BATCH * NF2, 128>>>();
    k_lin<<<(BATCH * 10 + 255) / 256, 256>>>(w_lin, b_lin, out);
}

// round 5
// speedup vs baseline: 3.2459x; 1.3901x over previous
#include <cuda_runtime.h>
#include <cuda_bf16.h>
#include <math.h>

#define PI_D 3.14159265358979323846

#define BATCH 128
#define NF2 40

// ---------------- device tables ----------------
__device__ double g_lf[64];
__device__ double g_w30[60];
__device__ double g_w10[20];
__device__ float  g_w2n[12];

__device__ float2 g_T60[10 * 60];        // e^{-2pi i m a/60}, m=0..9
__device__ float2 g_E20P[19 * 20];       // e^{+2pi i (ni-9) x/20}
__device__ float2 g_E20M[11 * 20];       // e^{-2pi i (mi-5) x/20}
__device__ float2 g_E12P[11 * 12];       // e^{+2pi i (ni-5) x/12}

__device__ float  g_wd_s2[10 * 60 * 10];     // [l][b][m]
__device__ float  g_d1w[10 * 20 * 10 * 19];  // [l][b][m][ni]
__device__ float  g_d12w[6 * 20 * 6 * 11];   // [l][b][m][ki]
__device__ float  g_d2w[6 * 12 * 6 * 11];    // [l][b][m][ni]
__device__ float2 g_Y1[10 * 24 * 19];        // [l][g][ni]
__device__ float2 g_D2[6 * 144 * 11 * 11];   // [l][g][ki][ni]

__device__ __align__(16) float2 g_E1[20 * 20 * 2000]; // [o][b][(m*20+g)*10+l]
__device__ __align__(16) float2 g_X[BATCH * 100];     // [z][m*10+l]
__device__ float2 g_Yg[(size_t)BATCH * 20 * 20 * 66]; // [z][c][b][m*11+ni]
__device__ __align__(16) float2 g_Fx[(size_t)128 * 3220]; // packed [p][z][ik]
__device__ __align__(16) float2 g_B2[316800];         // packed [l][ik][o*11+ni]
__device__ float2 g_Fo[(size_t)BATCH * NF2 * 21 * 11];// [z][o][p][ni]
__device__ float  g_feat[BATCH * NF2];

// p = (l,m) valid pairs, m<=l<=5
__constant__ int cPl[21]   = {0,1,1,2,2,2,3,3,3,3,4,4,4,4,4,5,5,5,5,5,5};
__constant__ int cPm[21]   = {0,0,1,0,1,2,0,1,2,3,0,1,2,3,4,0,1,2,3,4,5};
__constant__ int cPref[21] = {0,20,80,140,240,340,440,580,720,860,1000,1180,1360,1540,1720,1900,2120,2340,2560,2780,3000};
__constant__ int cOutOff[22] = {0,1,4,7,12,17,22,29,36,43,50,59,68,77,86,95,106,117,128,139,150,161};
__constant__ int cBl[36]  = {0,1,1,1,2,2,2,2,2,3,3,3,3,3,3,3,4,4,4,4,4,4,4,4,4,5,5,5,5,5,5,5,5,5,5,5};
__constant__ int cBkk[36] = {0,0,1,2,0,1,2,3,4,0,1,2,3,4,5,6,0,1,2,3,4,5,6,7,8,0,1,2,3,4,5,6,7,8,9,10};

__device__ __forceinline__ float fpow_i(float x, int p) {
    float r = 1.f;
    for (int i = 0; i < p; ++i) r *= x;
    return r;
}

__device__ float wigf(int l, int m, int n, double beta) {
    if (m > l || m < -l || n > l || n < -l) return 0.f;
    float cb = (float)cos(0.5 * beta), sb = (float)sin(0.5 * beta);
    float pref = (float)(0.5 * (g_lf[l + m] + g_lf[l - m] + g_lf[l + n] + g_lf[l - n]));
    int s0 = max(0, n - m), s1 = min(l + n, l - m);
    float acc = 0.f;
    for (int s = s0; s <= s1; ++s) {
        float c = pref - (float)(g_lf[l + n - s] + g_lf[s] + g_lf[m - n + s] + g_lf[l - m - s]);
        float t = expf(c) * fpow_i(cb, 2 * l + n - m - 2 * s) * fpow_i(sb, m - n + 2 * s);
        acc += ((m - n + s) & 1) ? -t : t;
    }
    return acc;
}

__device__ double dh_w_val(int bsz, int k) {
    double beta = PI_D * (2 * k + 1) / (4.0 * bsz);
    double s = 0.0;
    for (int j = 0; j < bsz; ++j)
        s += sin((2 * j + 1) * beta) / (2 * j + 1);
    return (2.0 / bsz) * sin(beta) * s;
}

// ---------------- setup 1 ----------------
__global__ void k_setup1() {
    int idx = blockIdx.x * blockDim.x + threadIdx.x;
    if (idx < 600) {
        int m = idx / 60, a = idx % 60;
        double th = -2.0 * PI_D * m * a / 60.0;
        g_T60[idx] = make_float2((float)cos(th), (float)sin(th));
    } else if (idx < 980) {
        int r = idx - 600; int ni = r / 20, x = r % 20;
        double th = 2.0 * PI_D * (ni - 9) * x / 20.0;
        g_E20P[r] = make_float2((float)cos(th), (float)sin(th));
    } else if (idx < 1200) {
        int r = idx - 980; int mi = r / 20, x = r % 20;
        double th = -2.0 * PI_D * (mi - 5) * x / 20.0;
        g_E20M[r] = make_float2((float)cos(th), (float)sin(th));
    } else if (idx < 1332) {
        int r = idx - 1200; int ni = r / 12, x = r % 12;
        double th = 2.0 * PI_D * (ni - 5) * x / 12.0;
        g_E12P[r] = make_float2((float)cos(th), (float)sin(th));
    } else if (idx < 1392) {
        g_w30[idx - 1332] = dh_w_val(30, idx - 1332);
    } else if (idx < 1412) {
        g_w10[idx - 1392] = dh_w_val(10, idx - 1392);
    } else if (idx < 1424) {
        int k = idx - 1412;
        double s = 0.0;
        for (int j = 0; j < 12; ++j) s += dh_w_val(6, j);
        g_w2n[k] = (float)(dh_w_val(6, k) / s);
    } else if (idx < 1465) {
        int n = idx - 1424;
        g_lf[n] = lgamma(n + 1.0);
    }
}

// ---------------- setup 2 ----------------
#define O_D1W  6000
#define O_D12W 44000
#define O_D2W  51920
#define O_Y1s  56672
#define O_D2s  61232
#define N_SET2 165776

__global__ void k_setup2() {
    int idx = blockIdx.x * blockDim.x + threadIdx.x;
    if (idx >= N_SET2) return;
    if (idx < O_D1W) {
        int i = idx;
        int l = i / 600, b = (i % 600) / 10, m = i % 10;
        double beta = PI_D * (2 * b + 1) / 120.0;
        g_wd_s2[i] = (float)g_w30[b] * wigf(l, m, 0, beta);
    } else if (idx < O_D12W) {
        int i = idx - O_D1W;
        int l = i / 3800; int r = i % 3800;
        int b = r / 190; int q = r % 190;
        int m = q / 19, ni = q % 19;
        double beta = PI_D * (2 * b + 1) / 40.0;
        g_d1w[i] = (2 * l + 1) * wigf(l, m, ni - 9, beta);
    } else if (idx < O_D2W) {
        int i = idx - O_D12W;
        int l = i / 1320; int r = i % 1320;
        int b = r / 66; int q = r % 66;
        int m = q / 11, ki = q % 11;
        double beta = PI_D * (2 * b + 1) / 40.0;
        g_d12w[i] = (float)g_w10[b] * wigf(l, m, ki - 5, beta);
    } else if (idx < O_Y1s) {
        int i = idx - O_D2W;
        int l = i / 792; int r = i % 792;
        int b = r / 66; int q = r % 66;
        int m = q / 11, ni = q % 11;
        double beta = PI_D * (2 * b + 1) / 24.0;
        g_d2w[i] = (2 * l + 1) * wigf(l, m, ni - 5, beta);
    } else if (idx < O_D2s) {
        int i = idx - O_Y1s;
        int l = i / (24 * 19); int r = i % (24 * 19);
        int g = r / 19, mi = r % 19;
        int ib = g / 8, ja = g % 8;
        double beta = (ib + 1) * PI_D / 24.0;
        double alpha = 2.0 * PI_D * ja / 8.0;
        int m = mi - 9;
        float d = wigf(l, m, 0, beta);
        double th = -(double)m * alpha;
        g_Y1[i] = make_float2(d * (float)cos(th), d * (float)sin(th));
    } else {
        int i = idx - O_D2s;
        int l = i / (144 * 121); int r = i % (144 * 121);
        int g = r / 121; int q = r % 121;
        int ki = q / 11, ni = q % 11;
        int ib = g / 48, ja = (g / 6) % 8, kg = g % 6;
        double beta = (ib + 1) * PI_D / 24.0;
        double alpha = 2.0 * PI_D * ja / 8.0;
        double gamma = 2.0 * PI_D * kg / 6.0;
        int m = ki - 5, n = ni - 5;
        float d = wigf(l, m, n, beta);
        double th = -((double)m * alpha + (double)n * gamma);
        g_D2[i] = make_float2(d * (float)cos(th), d * (float)sin(th));
    }
}

// ---------------- E1 (psi1 folded in): grid (b=20, o=20) ----------------
__global__ void k_E1(const float* __restrict__ psi1) {
    __shared__ float2 sPsi[190];     // [l][ni]
    __shared__ float  sd1w[1900];    // [l][m][ni]
    __shared__ float2 sE20P[380];    // [ni][g]
    int b = blockIdx.x, o = blockIdx.y;
    int tid = threadIdx.x;
    for (int t = tid; t < 190; t += 256) {
        int l = t / 19, ni = t % 19;
        float2 acc = make_float2(0.f, 0.f);
        for (int g = 0; g < 24; ++g) {
            float w = psi1[o * 24 + g];
            float2 y = g_Y1[(l * 24 + g) * 19 + ni];
            acc.x += w * y.x; acc.y += w * y.y;
        }
        sPsi[t] = acc;
    }
    for (int t = tid; t < 1900; t += 256) {
        int l = t / 190, m = (t / 19) % 10, ni = t % 19;
        sd1w[t] = g_d1w[((l * 20 + b) * 10 + m) * 19 + ni];
    }
    for (int t = tid; t < 380; t += 256) sE20P[t] = g_E20P[t];
    __syncthreads();
    for (int t = tid; t < 2000; t += 256) {
        int l = t % 10;
        int g = (t / 10) % 20;
        int m = t / 200;
        float2 acc = make_float2(0.f, 0.f);
        const float* dw = &sd1w[(l * 10 + m) * 19];
        const float2* ps = &sPsi[l * 19];
        for (int ni = 0; ni < 19; ++ni) {
            float d = dw[ni];
            float2 p = ps[ni];
            float2 e = sE20P[ni * 20 + g];
            acc.x += d * (p.x * e.x - p.y * e.y);
            acc.y += d * (p.x * e.y + p.y * e.x);
        }
        g_E1[(size_t)(o * 20 + b) * 2000 + t] = acc;
    }
}

// ---------------- B2 packed: grid (36, 8), 100 rows/block ----------------
__global__ void k_B2(const float* __restrict__ psi2) {
    int blk = blockIdx.x;
    int l = cBl[blk], kk = cBkk[blk];
    int kidx = kk - l + 5;
    __shared__ float2 sD[144 * 11];
    for (int t = threadIdx.x; t < 144 * 11; t += 128) {
        int g = t / 11, ni = t % 11;
        sD[t] = g_D2[((l * 144 + g) * 11 + kidx) * 11 + ni];
    }
    __syncthreads();
    if (threadIdx.x >= 100) return;
    int pr = blockIdx.y * 100 + threadIdx.x;
    size_t boff = (size_t)8800 * l * l;
    int i = pr / 40, o = pr % 40;
    float2 acc[11];
    #pragma unroll
    for (int ni = 0; ni < 11; ++ni) acc[ni] = make_float2(0.f, 0.f);
    const float* pp = psi2 + (size_t)pr * 144;
    for (int g = 0; g < 144; ++g) {
        float w = pp[g];
        const float2* dp = &sD[g * 11];
        #pragma unroll
        for (int ni = 0; ni < 11; ++ni) {
            acc[ni].x += w * dp[ni].x;
            acc[ni].y += w * dp[ni].y;
        }
    }
    size_t rb = boff + (size_t)(i * (2 * l + 1) + kk) * 440 + o * 11;
    #pragma unroll
    for (int ni = 0; ni < 11; ++ni) g_B2[rb + ni] = acc[ni];
}

// ---------------- X[z][m*10+l] ----------------
__global__ void k_X(const float* __restrict__ x) {
    __shared__ float sx[3600];
    __shared__ float2 sxf[600]; // [b][m]
    int z = blockIdx.x;
    for (int t = threadIdx.x; t < 3600; t += blockDim.x)
        sx[t] = x[(size_t)z * 3600 + t];
    __syncthreads();
    for (int t = threadIdx.x; t < 600; t += blockDim.x) {
        int b = t / 10, m = t % 10;
        float re = 0.f, im = 0.f;
        const float* row = &sx[b * 60];
        const float2* tw = &g_T60[m * 60];
        for (int a = 0; a < 60; ++a) {
            float v = row[a];
            re += v * tw[a].x; im += v * tw[a].y;
        }
        sxf[t] = make_float2(re, im);
    }
    __syncthreads();
    for (int t = threadIdx.x; t < 100; t += blockDim.x) {
        int l = t / 10, m = t % 10;
        float2 acc = make_float2(0.f, 0.f);
        for (int b = 0; b < 60; ++b) {
            float w = g_wd_s2[(l * 60 + b) * 10 + m];
            float2 v = sxf[b * 10 + m];
            acc.x += w * v.x; acc.y += w * v.y;
        }
        g_X[z * 100 + m * 10 + l] = acc; // [z][m][l]
    }
}

// ---------------- fused mid (radix-2, in-place A butterfly; 47.5KB smem) ----------------
__global__ __launch_bounds__(320) void k_mid() {
    __shared__ __align__(16) float2 sE1[2000]; // [m][g][l]          16000 B
    __shared__ float2 sTw1[200];               // [m][a], x2 m>=1     1600 B
    __shared__ float2 sEm[220];                // [mi][x]             1760 B
    __shared__ __align__(16) float2 sX[1600];  // [zz][m*10+l]       12800 B
    __shared__ float2 sA[1920];                // [zz][m2*20+g]      15360 B
    int b = blockIdx.x, c = blockIdx.y;
    int tid = threadIdx.x;
    const float2* e1 = g_E1 + (size_t)(c * 20 + b) * 2000;
    for (int t = tid; t < 2000; t += 320) sE1[t] = e1[t];
    for (int t = tid; t < 200; t += 320) {
        int m = t / 20;
        float2 e = g_E20P[(m + 9) * 20 + t % 20];
        float s = (m >= 1) ? 2.f : 1.f;
        sTw1[t] = make_float2(s * e.x, s * e.y);
    }
    for (int t = tid; t < 220; t += 320) sEm[t] = g_E20M[t];
    __syncthreads();
    int zz = tid / 20, g = tid % 20;
    for (int stage = 0; stage < 8; ++stage) {
        int z0 = stage * 16;
        for (int t = tid; t < 1600; t += 320)
            sX[t] = g_X[(z0 + t / 100) * 100 + t % 100];
        __syncthreads();
        // S1[m] = sum_l X[m,l] * E1[m,g,l]
        float2 S1m[10];
        #pragma unroll
        for (int m = 0; m < 10; ++m) {
            const float4* xp = (const float4*)&sX[zz * 100 + m * 10];
            const float4* ep = (const float4*)&sE1[(m * 20 + g) * 10];
            float ar = 0.f, ai = 0.f;
            #pragma unroll
            for (int i = 0; i < 5; ++i) {
                float4 xv = xp[i];
                float4 ev = ep[i];
                ar += xv.x * ev.x - xv.y * ev.y;
                ai += xv.x * ev.y + xv.y * ev.x;
                ar += xv.z * ev.z - xv.w * ev.w;
                ai += xv.z * ev.w + xv.w * ev.z;
            }
            S1m[m] = make_float2(ar, ai);
        }
        // y[a], y[a+10] via even/odd m split; ys/yd in registers
        float ys[10], yd[10];
        #pragma unroll
        for (int a = 0; a < 10; ++a) {
            float ve = S1m[0].x, vo = 0.f;
            #pragma unroll
            for (int m = 1; m < 10; ++m) {
                float2 e = sTw1[m * 20 + a]; // includes x2
                float tt = S1m[m].x * e.x - S1m[m].y * e.y;
                if (m & 1) vo += tt; else ve += tt;
            }
            float y0 = fmaxf(ve + vo, 0.f);
            float y1 = fmaxf(ve - vo, 0.f);
            ys[a] = y0 + y1;
            yd[a] = y0 - y1;
        }
        // A[m2] = sum_{a=0..9} (ys|yd)[a] e^{-i m2 a}
        #pragma unroll
        for (int m2 = 0; m2 < 6; ++m2) {
            const float2* ep = &sEm[(m2 + 5) * 20];
            const float* yy = (m2 & 1) ? yd : ys;
            float ar = 0.f, ai = 0.f;
            #pragma unroll
            for (int a = 0; a < 10; ++a) {
                ar += yy[a] * ep[a].x;
                ai += yy[a] * ep[a].y;
            }
            sA[zz * 120 + m2 * 20 + g] = make_float2(ar, ai);
        }
        __syncthreads();
        // in-place gamma butterfly: slot a <- A[a]+A[a+10], slot a+10 <- A[a]-A[a+10]
        for (int t = tid; t < 960; t += 320) {
            int zz2 = t / 60, m2 = (t / 10) % 6, a = t % 10;
            int base = zz2 * 120 + m2 * 20;
            float2 p = sA[base + a];
            float2 q = sA[base + a + 10];
            sA[base + a]      = make_float2(p.x + q.x, p.y + q.y);
            sA[base + a + 10] = make_float2(p.x - q.x, p.y - q.y);
        }
        __syncthreads();
        // Yg[m,n] = sum_{g=0..9} (As|Ad)[g] e^{-i n g}
        for (int t = tid; t < 1056; t += 320) {
            int zz2 = t / 66, r = t % 66;
            int m = r / 11, ni = r % 11;
            int odd = (ni - 5) & 1;
            const float2* ap = &sA[zz2 * 120 + m * 20 + odd * 10];
            const float2* ep = &sEm[ni * 20];
            float2 acc = make_float2(0.f, 0.f);
            #pragma unroll
            for (int gg = 0; gg < 10; ++gg) {
                float2 av = ap[gg], e = ep[gg];
                acc.x += av.x * e.x - av.y * e.y;
                acc.y += av.x * e.y + av.y * e.x;
            }
            int z = z0 + zz2;
            g_Yg[((size_t)((z * 20 + c) * 20 + b)) * 66 + r] = acc;
        }
        __syncthreads();
    }
}

// ---------------- Fx packed ----------------
__global__ void k_Fx() {
    __shared__ float2 sYs[1320]; // [b][m*11+ni]
    int zi = blockIdx.x;
    int z = zi / 20, i = zi % 20;
    for (int t = threadIdx.x; t < 1320; t += blockDim.x)
        sYs[t] = g_Yg[(size_t)zi * 1320 + t];
    __syncthreads();
    int t = threadIdx.x;
    if (t < 161) {
        int p = 0;
        while (t >= cOutOff[p + 1]) ++p;
        int kk = t - cOutOff[p];
        int l = cPl[p], m = cPm[p];
        int kidx = kk - l + 5;
        float2 acc = make_float2(0.f, 0.f);
        #pragma unroll
        for (int b = 0; b < 20; ++b) {
            float d = g_d12w[((l * 20 + b) * 6 + m) * 11 + kidx];
            float2 v = sYs[b * 66 + m * 11 + kidx];
            acc.x += d * v.x; acc.y += d * v.y;
        }
        int Kl = 20 * (2 * l + 1);
        g_Fx[(size_t)cPref[p] * 128 + (size_t)z * Kl + i * (2 * l + 1) + kk] = acc;
    }
}

// ---------------- Fo GEMM (heavy-l first, ik-paired float4) ----------------
#define FO_ZT 8
__global__ void k_Fo() {
    __shared__ __align__(16) float2 sAa[FO_ZT * 220];
    int p = 20 - blockIdx.x;
    int z0 = blockIdx.y * FO_ZT;
    int l = cPl[p];
    int Kl = 20 * (2 * l + 1);
    size_t abase = (size_t)cPref[p] * 128 + (size_t)z0 * Kl;
    for (int t = threadIdx.x; t < FO_ZT * Kl; t += blockDim.x)
        sAa[t] = g_Fx[abase + t];
    __syncthreads();
    int t = threadIdx.x;
    if (t < 220) {
        float2 a0[FO_ZT], a1[FO_ZT];
        #pragma unroll
        for (int zz = 0; zz < FO_ZT; ++zz) { a0[zz] = make_float2(0.f, 0.f); a1[zz] = make_float2(0.f, 0.f); }
        const float4* Bp = (const float4*)(g_B2 + (size_t)8800 * l * l);
        const float4* Ap = (const float4*)sAa;
        for (int ik = 0; ik < Kl; ik += 2) {
            float4 b0 = Bp[ik * 220 + t];
            float4 b1 = Bp[(ik + 1) * 220 + t];
            #pragma unroll
            for (int zz = 0; zz < FO_ZT; ++zz) {
                float4 av = Ap[(zz * Kl + ik) >> 1]; // (re0,im0,re1,im1)
                a0[zz].x += av.x * b0.x - av.y * b0.y;
                a0[zz].y += av.x * b0.y + av.y * b0.x;
                a1[zz].x += av.x * b0.z - av.y * b0.w;
                a1[zz].y += av.x * b0.w + av.y * b0.z;
                a0[zz].x += av.z * b1.x - av.w * b1.y;
                a0[zz].y += av.z * b1.y + av.w * b1.x;
                a1[zz].x += av.z * b1.z - av.w * b1.w;
                a1[zz].y += av.z * b1.w + av.w * b1.z;
            }
        }
        int o0 = (2 * t) / 11, n0 = (2 * t) % 11;
        int o1 = (2 * t + 1) / 11, n1 = (2 * t + 1) % 11;
        #pragma unroll
        for (int zz = 0; zz < FO_ZT; ++zz) {
            int z = z0 + zz;
            g_Fo[((size_t)(z * 40 + o0) * 21 + p) * 11 + n0] = a0[zz];
            g_Fo[((size_t)(z * 40 + o1) * 21 + p) * 11 + n1] = a1[zz];
        }
    }
}

// ---------------- final (radix-2 on both 12-pt stages) ----------------
__global__ void k_final() {
    __shared__ float2 sFo[231];
    __shared__ float2 sE12[132];
    __shared__ float2 sFh2[792];  // [(b*6+m)*11+ni]
    __shared__ float2 sU[864];    // [(b*6+m)*12+g]
    __shared__ float  sw2[12];
    __shared__ float  sred[128];
    int zo = blockIdx.x;
    int tid = threadIdx.x;
    for (int t = tid; t < 231; t += 128) sFo[t] = g_Fo[(size_t)zo * 231 + t];
    for (int t = tid; t < 132; t += 128) sE12[t] = g_E12P[t];
    if (tid < 12) sw2[tid] = g_w2n[tid];
    __syncthreads();
    for (int t = tid; t < 792; t += 128) {
        int b = t / 66, r = t % 66;
        int m = r / 11, ni = r % 11;
        float2 acc = make_float2(0.f, 0.f);
        for (int l = m; l < 6; ++l) {
            float d = g_d2w[((l * 12 + b) * 6 + m) * 11 + ni];
            float2 f = sFo[(l * (l + 1) / 2 + m) * 11 + ni];
            acc.x += d * f.x; acc.y += d * f.y;
        }
        sFh2[(b * 6 + m) * 11 + ni] = acc;
    }
    __syncthreads();
    // gamma synthesis: pairs (g, g+6) via parity of (ni-5)
    for (int t = tid; t < 432; t += 128) {
        int bm = t / 6, g = t % 6;
        float2 ue = make_float2(0.f, 0.f), uo = make_float2(0.f, 0.f);
        const float2* fp = &sFh2[bm * 11];
        #pragma unroll
        for (int ni = 0; ni < 11; ++ni) {
            float2 f = fp[ni];
            float2 e = sE12[ni * 12 + g];
            float tr = f.x * e.x - f.y * e.y;
            float ti = f.x * e.y + f.y * e.x;
            if ((ni - 5) & 1) { uo.x += tr; uo.y += ti; }
            else              { ue.x += tr; ue.y += ti; }
        }
        sU[bm * 12 + g]     = make_float2(ue.x + uo.x, ue.y + uo.y);
        sU[bm * 12 + g + 6] = make_float2(ue.x - uo.x, ue.y - uo.y);
    }
    __syncthreads();
    // alpha synthesis (Hermitian + pair a,a+6) + relu + quadrature
    float part = 0.f;
    for (int t = tid; t < 864; t += 128) {
        int bq = t / 72, r = t % 72;
        int a = r / 12, g = r % 12;
        const float2* up = &sU[bq * 72 + g];
        float ve = up[0].x, vo = 0.f;
        #pragma unroll
        for (int m = 1; m < 6; ++m) {
            float2 u = up[m * 12];
            float2 e = sE12[(m + 5) * 12 + a];
            float tt = 2.f * (u.x * e.x - u.y * e.y);
            if (m & 1) vo += tt; else ve += tt;
        }
        float v0 = ve + vo, v1 = ve - vo;
        float s = 0.f;
        if (v0 > 0.f) s += v0;
        if (v1 > 0.f) s += v1;
        part += sw2[bq] * s;
    }
    sred[tid] = part;
    __syncthreads();
    for (int s = 64; s > 0; s >>= 1) {
        if (tid < s) sred[tid] += sred[tid + s];
        __syncthreads();
    }
    if (tid == 0) g_feat[zo] = sred[0] * (1.0f / 144.0f);
}

// ---------------- linear head ----------------
__global__ void k_lin(const float* __restrict__ w_lin, const float* __restrict__ b_lin,
                      float* __restrict__ out) {
    int t = blockIdx.x * blockDim.x + threadIdx.x;
    if (t >= BATCH * 10) return;
    int z = t / 10, f = t % 10;
    float acc = b_lin[f];
    #pragma unroll
    for (int o = 0; o < NF2; ++o)
        acc += g_feat[z * NF2 + o] * w_lin[f * NF2 + o];
    out[t] = acc;
}

// ---------------- launch ----------------
extern "C" void kernel_launch(void* const* d_in, const int* in_sizes, int n_in,
                              void* d_out, int out_size) {
    const float* x     = (const float*)d_in[0];
    const float* psi1  = (const float*)d_in[1];
    const float* psi2  = (const float*)d_in[2];
    const float* w_lin = (const float*)d_in[3];
    const float* b_lin = (const float*)d_in[4];
    float* out = (float*)d_out;

    k_setup1<<<6, 256>>>();
    k_setup2<<<(N_SET2 + 255) / 256, 256>>>();
    k_E1<<<dim3(20, 20), 256>>>(psi1);
    k_B2<<<dim3(36, 8), 128>>>(psi2);
    k_X<<<BATCH, 256>>>(x);
    k_mid<<<dim3(20, 20), 320>>>();
    k_Fx<<<BATCH * 20, 192>>>();
    k_Fo<<<dim3(21, BATCH / FO_ZT), 256>>>();
    k_final<<<BATCH * NF2, 128>>>();
    k_lin<<<(BATCH * 10 + 255) / 256, 256>>>(w_lin, b_lin, out);
}

// round 6
// speedup vs baseline: 3.4405x; 1.0599x over previous
#include <cuda_runtime.h>
#include <cuda_bf16.h>
#include <math.h>

#define PI_D 3.14159265358979323846

#define BATCH 128
#define NF2 40

// ---------------- device tables ----------------
__device__ float  g_w2n[12];

__device__ float2 g_T60[10 * 60];        // e^{-2pi i m a/60}, m=0..9
__device__ float2 g_E20P[19 * 20];       // e^{+2pi i (ni-9) x/20}
__device__ float2 g_E20M[11 * 20];       // e^{-2pi i (mi-5) x/20}
__device__ float2 g_E12P[11 * 12];       // e^{+2pi i (ni-5) x/12}

__device__ float  g_wd_s2[10 * 60 * 10];     // [l][b][m]
__device__ float  g_d1w[10 * 20 * 10 * 19];  // [l][b][m][ni]
__device__ float  g_d12w[6 * 20 * 6 * 11];   // [l][b][m][ki]
__device__ float  g_d2w[6 * 12 * 6 * 11];    // [l][b][m][ni]
__device__ float2 g_Y1[10 * 24 * 19];        // [l][g][ni]
__device__ float2 g_D2[6 * 144 * 11 * 11];   // [l][g][ki][ni]

__device__ __align__(16) float2 g_E1[20 * 20 * 2000]; // [o][b][(m*20+g)*10+l]
__device__ __align__(16) float2 g_X[BATCH * 100];     // [z][m*10+l]
__device__ float2 g_Yg[(size_t)BATCH * 20 * 20 * 66]; // [z][c][b][m*11+ni]
__device__ __align__(16) float2 g_Fx[(size_t)128 * 3220]; // packed [p][z][ik]
__device__ __align__(16) float2 g_B2[316800];         // packed [l][ik][o*11+ni]
__device__ float2 g_Fo[(size_t)BATCH * NF2 * 21 * 11];// [z][o][p][ni]
__device__ float  g_feat[BATCH * NF2];

// p = (l,m) valid pairs, m<=l<=5
__constant__ int cPl[21]   = {0,1,1,2,2,2,3,3,3,3,4,4,4,4,4,5,5,5,5,5,5};
__constant__ int cPref[21] = {0,20,80,140,240,340,440,580,720,860,1000,1180,1360,1540,1720,1900,2120,2340,2560,2780,3000};
__constant__ int cOutOff[22] = {0,1,4,7,12,17,22,29,36,43,50,59,68,77,86,95,106,117,128,139,150,161};
__constant__ int cPm[21]   = {0,0,1,0,1,2,0,1,2,3,0,1,2,3,4,0,1,2,3,4,5};
__constant__ int cBl[36]  = {0,1,1,1,2,2,2,2,2,3,3,3,3,3,3,3,4,4,4,4,4,4,4,4,4,5,5,5,5,5,5,5,5,5,5,5};
__constant__ int cBkk[36] = {0,0,1,2,0,1,2,3,4,0,1,2,3,4,5,6,0,1,2,3,4,5,6,7,8,0,1,2,3,4,5,6,7,8,9,10};

__device__ __forceinline__ float fpow_i(float x, int p) {
    float r = 1.f;
    for (int i = 0; i < p; ++i) r *= x;
    return r;
}

__device__ float wigf(const double* lf, int l, int m, int n, double beta) {
    if (m > l || m < -l || n > l || n < -l) return 0.f;
    float cb = (float)cos(0.5 * beta), sb = (float)sin(0.5 * beta);
    float pref = (float)(0.5 * (lf[l + m] + lf[l - m] + lf[l + n] + lf[l - n]));
    int s0 = max(0, n - m), s1 = min(l + n, l - m);
    float acc = 0.f;
    for (int s = s0; s <= s1; ++s) {
        float c = pref - (float)(lf[l + n - s] + lf[s] + lf[m - n + s] + lf[l - m - s]);
        float t = expf(c) * fpow_i(cb, 2 * l + n - m - 2 * s) * fpow_i(sb, m - n + 2 * s);
        acc += ((m - n + s) & 1) ? -t : t;
    }
    return acc;
}

__device__ double dh_w_val(int bsz, int k) {
    double beta = PI_D * (2 * k + 1) / (4.0 * bsz);
    double s = 0.0;
    for (int j = 0; j < bsz; ++j)
        s += sin((2 * j + 1) * beta) / (2 * j + 1);
    return (2.0 / bsz) * sin(beta) * s;
}

// ---------------- merged setup ----------------
#define O_D1W  6000
#define O_D12W 44000
#define O_D2W  51920
#define O_Y1s  56672
#define O_D2s  61232
#define N_SET2 165776
#define SET_TAB_BASE 2048

__global__ void k_setup() {
    __shared__ double s_lf[64];
    int tid = threadIdx.x;
    if (tid < 64) s_lf[tid] = lgamma(tid + 1.0);
    __syncthreads();
    int idx = blockIdx.x * blockDim.x + tid;
    if (idx < 1344) {
        if (idx < 600) {
            int m = idx / 60, a = idx % 60;
            double th = -2.0 * PI_D * m * a / 60.0;
            g_T60[idx] = make_float2((float)cos(th), (float)sin(th));
        } else if (idx < 980) {
            int r = idx - 600; int ni = r / 20, x = r % 20;
            double th = 2.0 * PI_D * (ni - 9) * x / 20.0;
            g_E20P[r] = make_float2((float)cos(th), (float)sin(th));
        } else if (idx < 1200) {
            int r = idx - 980; int mi = r / 20, x = r % 20;
            double th = -2.0 * PI_D * (mi - 5) * x / 20.0;
            g_E20M[r] = make_float2((float)cos(th), (float)sin(th));
        } else if (idx < 1332) {
            int r = idx - 1200; int ni = r / 12, x = r % 12;
            double th = 2.0 * PI_D * (ni - 5) * x / 12.0;
            g_E12P[r] = make_float2((float)cos(th), (float)sin(th));
        } else {
            int k = idx - 1332;
            double s = 0.0;
            for (int j = 0; j < 12; ++j) s += dh_w_val(6, j);
            g_w2n[k] = (float)(dh_w_val(6, k) / s);
        }
        return;
    }
    if (idx < SET_TAB_BASE) return;
    int i2 = idx - SET_TAB_BASE;
    if (i2 >= N_SET2) return;
    if (i2 < O_D1W) {
        int i = i2;
        int l = i / 600, b = (i % 600) / 10, m = i % 10;
        double beta = PI_D * (2 * b + 1) / 120.0;
        g_wd_s2[i] = (float)dh_w_val(30, b) * wigf(s_lf, l, m, 0, beta);
    } else if (i2 < O_D12W) {
        int i = i2 - O_D1W;
        int l = i / 3800; int r = i % 3800;
        int b = r / 190; int q = r % 190;
        int m = q / 19, ni = q % 19;
        double beta = PI_D * (2 * b + 1) / 40.0;
        g_d1w[i] = (2 * l + 1) * wigf(s_lf, l, m, ni - 9, beta);
    } else if (i2 < O_D2W) {
        int i = i2 - O_D12W;
        int l = i / 1320; int r = i % 1320;
        int b = r / 66; int q = r % 66;
        int m = q / 11, ki = q % 11;
        double beta = PI_D * (2 * b + 1) / 40.0;
        g_d12w[i] = (float)dh_w_val(10, b) * wigf(s_lf, l, m, ki - 5, beta);
    } else if (i2 < O_Y1s) {
        int i = i2 - O_D2W;
        int l = i / 792; int r = i % 792;
        int b = r / 66; int q = r % 66;
        int m = q / 11, ni = q % 11;
        double beta = PI_D * (2 * b + 1) / 24.0;
        g_d2w[i] = (2 * l + 1) * wigf(s_lf, l, m, ni - 5, beta);
    } else if (i2 < O_D2s) {
        int i = i2 - O_Y1s;
        int l = i / (24 * 19); int r = i % (24 * 19);
        int g = r / 19, mi = r % 19;
        int ib = g / 8, ja = g % 8;
        double beta = (ib + 1) * PI_D / 24.0;
        double alpha = 2.0 * PI_D * ja / 8.0;
        int m = mi - 9;
        float d = wigf(s_lf, l, m, 0, beta);
        double th = -(double)m * alpha;
        g_Y1[i] = make_float2(d * (float)cos(th), d * (float)sin(th));
    } else {
        int i = i2 - O_D2s;
        int l = i / (144 * 121); int r = i % (144 * 121);
        int g = r / 121; int q = r % 121;
        int ki = q / 11, ni = q % 11;
        int ib = g / 48, ja = (g / 6) % 8, kg = g % 6;
        double beta = (ib + 1) * PI_D / 24.0;
        double alpha = 2.0 * PI_D * ja / 8.0;
        double gamma = 2.0 * PI_D * kg / 6.0;
        int m = ki - 5, n = ni - 5;
        float d = wigf(s_lf, l, m, n, beta);
        double th = -((double)m * alpha + (double)n * gamma);
        g_D2[i] = make_float2(d * (float)cos(th), d * (float)sin(th));
    }
}

// ---------------- merged prep: E1 (blocks 0..399), B2 (400..1839), X (1840..1967) ----------------
#define PREP_E1_N 400
#define PREP_B2_N 1440
#define PREP_X_BASE (PREP_E1_N + PREP_B2_N)
#define PREP_TOTAL (PREP_X_BASE + BATCH)

__global__ __launch_bounds__(256) void k_prep(const float* __restrict__ psi1,
                                              const float* __restrict__ psi2,
                                              const float* __restrict__ x) {
    __shared__ __align__(16) char sbuf[24576];
    int blk = blockIdx.x;
    int tid = threadIdx.x;

    if (blk < PREP_E1_N) {
        // ---- E1: b = blk % 20, o = blk / 20 ----
        int b = blk % 20, o = blk / 20;
        float2* sPsi  = (float2*)sbuf;                 // 190
        float*  sd1w  = (float*)(sbuf + 1520);         // 1900
        float2* sE20P = (float2*)(sbuf + 9120);        // 380
        for (int t = tid; t < 190; t += 256) {
            int l = t / 19, ni = t % 19;
            float2 acc = make_float2(0.f, 0.f);
            for (int g = 0; g < 24; ++g) {
                float w = psi1[o * 24 + g];
                float2 y = g_Y1[(l * 24 + g) * 19 + ni];
                acc.x += w * y.x; acc.y += w * y.y;
            }
            sPsi[t] = acc;
        }
        for (int t = tid; t < 1900; t += 256) {
            int l = t / 190, m = (t / 19) % 10, ni = t % 19;
            sd1w[t] = g_d1w[((l * 20 + b) * 10 + m) * 19 + ni];
        }
        for (int t = tid; t < 380; t += 256) sE20P[t] = g_E20P[t];
        __syncthreads();
        for (int t = tid; t < 2000; t += 256) {
            int l = t % 10;
            int g = (t / 10) % 20;
            int m = t / 200;
            float2 acc = make_float2(0.f, 0.f);
            const float* dw = &sd1w[(l * 10 + m) * 19];
            const float2* ps = &sPsi[l * 19];
            for (int ni = 0; ni < 19; ++ni) {
                float d = dw[ni];
                float2 p = ps[ni];
                float2 e = sE20P[ni * 20 + g];
                acc.x += d * (p.x * e.x - p.y * e.y);
                acc.y += d * (p.x * e.y + p.y * e.x);
            }
            g_E1[(size_t)(o * 20 + b) * 2000 + t] = acc;
        }
    } else if (blk < PREP_X_BASE) {
        // ---- B2 GEMM: slice s = (l,kk), rowgroup rg of 20 psi2-rows ----
        int q = blk - PREP_E1_N;
        int s = q / 40, rg = q % 40;
        int l = cBl[s], kk = cBkk[s];
        int kidx = kk - l + 5;
        float2* sD = (float2*)sbuf;                    // 1584 (12672 B)
        float*  sP = (float*)(sbuf + 12672);           // 20*145 (11600 B)
        for (int t = tid; t < 1584; t += 256) {
            int g = t / 11, ni = t % 11;
            sD[t] = g_D2[((l * 144 + g) * 11 + kidx) * 11 + ni];
        }
        int row0 = rg * 20;
        for (int t = tid; t < 20 * 144; t += 256) {
            int r = t / 144, g = t % 144;
            sP[r * 145 + g] = psi2[(size_t)(row0 + r) * 144 + g];
        }
        __syncthreads();
        if (tid < 220) {
            int rl = tid / 11, ni = tid % 11;
            int pr = row0 + rl;
            float2 acc = make_float2(0.f, 0.f);
            const float* pp = &sP[rl * 145];
            #pragma unroll 8
            for (int g = 0; g < 144; ++g) {
                float w = pp[g];
                float2 d = sD[g * 11 + ni];
                acc.x += w * d.x; acc.y += w * d.y;
            }
            int i = pr / 40, o = pr % 40;
            g_B2[(size_t)8800 * l * l + (size_t)(i * (2 * l + 1) + kk) * 440 + o * 11 + ni] = acc;
        }
    } else {
        // ---- X: z = blk - PREP_X_BASE ----
        int z = blk - PREP_X_BASE;
        float*  sx  = (float*)sbuf;                    // 3600 (14400 B)
        float2* sxf = (float2*)(sbuf + 14400);         // 600
        for (int t = tid; t < 3600; t += 256)
            sx[t] = x[(size_t)z * 3600 + t];
        __syncthreads();
        for (int t = tid; t < 600; t += 256) {
            int b = t / 10, m = t % 10;
            float re = 0.f, im = 0.f;
            const float* row = &sx[b * 60];
            const float2* tw = &g_T60[m * 60];
            for (int a = 0; a < 60; ++a) {
                float v = row[a];
                re += v * tw[a].x; im += v * tw[a].y;
            }
            sxf[t] = make_float2(re, im);
        }
        __syncthreads();
        for (int t = tid; t < 100; t += 256) {
            int l = t / 10, m = t % 10;
            float2 acc = make_float2(0.f, 0.f);
            for (int b = 0; b < 60; ++b) {
                float w = g_wd_s2[(l * 60 + b) * 10 + m];
                float2 v = sxf[b * 10 + m];
                acc.x += w * v.x; acc.y += w * v.y;
            }
            g_X[z * 100 + m * 10 + l] = acc;
        }
    }
}

// ---------------- fused mid (radix-2, in-place A butterfly) ----------------
__global__ __launch_bounds__(320) void k_mid() {
    __shared__ __align__(16) float2 sE1[2000]; // [m][g][l]
    __shared__ float2 sTw1[200];               // [m][a], x2 m>=1
    __shared__ float2 sEm[220];                // [mi][x]
    __shared__ __align__(16) float2 sX[1600];  // [zz][m*10+l]
    __shared__ float2 sA[1920];                // [zz][m2*20+g]
    int b = blockIdx.x, c = blockIdx.y;
    int tid = threadIdx.x;
    const float2* e1 = g_E1 + (size_t)(c * 20 + b) * 2000;
    for (int t = tid; t < 2000; t += 320) sE1[t] = e1[t];
    for (int t = tid; t < 200; t += 320) {
        int m = t / 20;
        float2 e = g_E20P[(m + 9) * 20 + t % 20];
        float s = (m >= 1) ? 2.f : 1.f;
        sTw1[t] = make_float2(s * e.x, s * e.y);
    }
    for (int t = tid; t < 220; t += 320) sEm[t] = g_E20M[t];
    __syncthreads();
    int zz = tid / 20, g = tid % 20;
    for (int stage = 0; stage < 8; ++stage) {
        int z0 = stage * 16;
        for (int t = tid; t < 1600; t += 320)
            sX[t] = g_X[(z0 + t / 100) * 100 + t % 100];
        __syncthreads();
        float2 S1m[10];
        #pragma unroll
        for (int m = 0; m < 10; ++m) {
            const float4* xp = (const float4*)&sX[zz * 100 + m * 10];
            const float4* ep = (const float4*)&sE1[(m * 20 + g) * 10];
            float ar = 0.f, ai = 0.f;
            #pragma unroll
            for (int i = 0; i < 5; ++i) {
                float4 xv = xp[i];
                float4 ev = ep[i];
                ar += xv.x * ev.x - xv.y * ev.y;
                ai += xv.x * ev.y + xv.y * ev.x;
                ar += xv.z * ev.z - xv.w * ev.w;
                ai += xv.z * ev.w + xv.w * ev.z;
            }
            S1m[m] = make_float2(ar, ai);
        }
        float ys[10], yd[10];
        #pragma unroll
        for (int a = 0; a < 10; ++a) {
            float ve = S1m[0].x, vo = 0.f;
            #pragma unroll
            for (int m = 1; m < 10; ++m) {
                float2 e = sTw1[m * 20 + a];
                float tt = S1m[m].x * e.x - S1m[m].y * e.y;
                if (m & 1) vo += tt; else ve += tt;
            }
            float y0 = fmaxf(ve + vo, 0.f);
            float y1 = fmaxf(ve - vo, 0.f);
            ys[a] = y0 + y1;
            yd[a] = y0 - y1;
        }
        #pragma unroll
        for (int m2 = 0; m2 < 6; ++m2) {
            const float2* ep = &sEm[(m2 + 5) * 20];
            const float* yy = (m2 & 1) ? yd : ys;
            float ar = 0.f, ai = 0.f;
            #pragma unroll
            for (int a = 0; a < 10; ++a) {
                ar += yy[a] * ep[a].x;
                ai += yy[a] * ep[a].y;
            }
            sA[zz * 120 + m2 * 20 + g] = make_float2(ar, ai);
        }
        __syncthreads();
        for (int t = tid; t < 960; t += 320) {
            int zz2 = t / 60, m2 = (t / 10) % 6, a = t % 10;
            int base = zz2 * 120 + m2 * 20;
            float2 p = sA[base + a];
            float2 q = sA[base + a + 10];
            sA[base + a]      = make_float2(p.x + q.x, p.y + q.y);
            sA[base + a + 10] = make_float2(p.x - q.x, p.y - q.y);
        }
        __syncthreads();
        for (int t = tid; t < 1056; t += 320) {
            int zz2 = t / 66, r = t % 66;
            int m = r / 11, ni = r % 11;
            int odd = (ni - 5) & 1;
            const float2* ap = &sA[zz2 * 120 + m * 20 + odd * 10];
            const float2* ep = &sEm[ni * 20];
            float2 acc = make_float2(0.f, 0.f);
            #pragma unroll
            for (int gg = 0; gg < 10; ++gg) {
                float2 av = ap[gg], e = ep[gg];
                acc.x += av.x * e.x - av.y * e.y;
                acc.y += av.x * e.y + av.y * e.x;
            }
            int z = z0 + zz2;
            g_Yg[((size_t)((z * 20 + c) * 20 + b)) * 66 + r] = acc;
        }
        __syncthreads();
    }
}

// ---------------- Fx packed ----------------
__global__ void k_Fx() {
    __shared__ float2 sYs[1320]; // [b][m*11+ni]
    int zi = blockIdx.x;
    int z = zi / 20, i = zi % 20;
    for (int t = threadIdx.x; t < 1320; t += blockDim.x)
        sYs[t] = g_Yg[(size_t)zi * 1320 + t];
    __syncthreads();
    int t = threadIdx.x;
    if (t < 161) {
        int p = 0;
        while (t >= cOutOff[p + 1]) ++p;
        int kk = t - cOutOff[p];
        int l = cPl[p], m = cPm[p];
        int kidx = kk - l + 5;
        float2 acc = make_float2(0.f, 0.f);
        #pragma unroll
        for (int b = 0; b < 20; ++b) {
            float d = g_d12w[((l * 20 + b) * 6 + m) * 11 + kidx];
            float2 v = sYs[b * 66 + m * 11 + kidx];
            acc.x += d * v.x; acc.y += d * v.y;
        }
        int Kl = 20 * (2 * l + 1);
        g_Fx[(size_t)cPref[p] * 128 + (size_t)z * Kl + i * (2 * l + 1) + kk] = acc;
    }
}

// ---------------- Fo GEMM (heavy-l first, ik-paired float4) ----------------
#define FO_ZT 8
__global__ void k_Fo() {
    __shared__ __align__(16) float2 sAa[FO_ZT * 220];
    int p = 20 - blockIdx.x;
    int z0 = blockIdx.y * FO_ZT;
    int l = cPl[p];
    int Kl = 20 * (2 * l + 1);
    size_t abase = (size_t)cPref[p] * 128 + (size_t)z0 * Kl;
    for (int t = threadIdx.x; t < FO_ZT * Kl; t += blockDim.x)
        sAa[t] = g_Fx[abase + t];
    __syncthreads();
    int t = threadIdx.x;
    if (t < 220) {
        float2 a0[FO_ZT], a1[FO_ZT];
        #pragma unroll
        for (int zz = 0; zz < FO_ZT; ++zz) { a0[zz] = make_float2(0.f, 0.f); a1[zz] = make_float2(0.f, 0.f); }
        const float4* Bp = (const float4*)(g_B2 + (size_t)8800 * l * l);
        const float4* Ap = (const float4*)sAa;
        for (int ik = 0; ik < Kl; ik += 2) {
            float4 b0 = Bp[ik * 220 + t];
            float4 b1 = Bp[(ik + 1) * 220 + t];
            #pragma unroll
            for (int zz = 0; zz < FO_ZT; ++zz) {
                float4 av = Ap[(zz * Kl + ik) >> 1];
                a0[zz].x += av.x * b0.x - av.y * b0.y;
                a0[zz].y += av.x * b0.y + av.y * b0.x;
                a1[zz].x += av.x * b0.z - av.y * b0.w;
                a1[zz].y += av.x * b0.w + av.y * b0.z;
                a0[zz].x += av.z * b1.x - av.w * b1.y;
                a0[zz].y += av.z * b1.y + av.w * b1.x;
                a1[zz].x += av.z * b1.z - av.w * b1.w;
                a1[zz].y += av.z * b1.w + av.w * b1.z;
            }
        }
        int o0 = (2 * t) / 11, n0 = (2 * t) % 11;
        int o1 = (2 * t + 1) / 11, n1 = (2 * t + 1) % 11;
        #pragma unroll
        for (int zz = 0; zz < FO_ZT; ++zz) {
            int z = z0 + zz;
            g_Fo[((size_t)(z * 40 + o0) * 21 + p) * 11 + n0] = a0[zz];
            g_Fo[((size_t)(z * 40 + o1) * 21 + p) * 11 + n1] = a1[zz];
        }
    }
}

// ---------------- final (radix-2 on both 12-pt stages) ----------------
__global__ void k_final() {
    __shared__ float2 sFo[231];
    __shared__ float2 sE12[132];
    __shared__ float2 sFh2[792];
    __shared__ float2 sU[864];
    __shared__ float  sw2[12];
    __shared__ float  sred[128];
    int zo = blockIdx.x;
    int tid = threadIdx.x;
    for (int t = tid; t < 231; t += 128) sFo[t] = g_Fo[(size_t)zo * 231 + t];
    for (int t = tid; t < 132; t += 128) sE12[t] = g_E12P[t];
    if (tid < 12) sw2[tid] = g_w2n[tid];
    __syncthreads();
    for (int t = tid; t < 792; t += 128) {
        int b = t / 66, r = t % 66;
        int m = r / 11, ni = r % 11;
        float2 acc = make_float2(0.f, 0.f);
        for (int l = m; l < 6; ++l) {
            float d = g_d2w[((l * 12 + b) * 6 + m) * 11 + ni];
            float2 f = sFo[(l * (l + 1) / 2 + m) * 11 + ni];
            acc.x += d * f.x; acc.y += d * f.y;
        }
        sFh2[(b * 6 + m) * 11 + ni] = acc;
    }
    __syncthreads();
    for (int t = tid; t < 432; t += 128) {
        int bm = t / 6, g = t % 6;
        float2 ue = make_float2(0.f, 0.f), uo = make_float2(0.f, 0.f);
        const float2* fp = &sFh2[bm * 11];
        #pragma unroll
        for (int ni = 0; ni < 11; ++ni) {
            float2 f = fp[ni];
            float2 e = sE12[ni * 12 + g];
            float tr = f.x * e.x - f.y * e.y;
            float ti = f.x * e.y + f.y * e.x;
            if ((ni - 5) & 1) { uo.x += tr; uo.y += ti; }
            else              { ue.x += tr; ue.y += ti; }
        }
        sU[bm * 12 + g]     = make_float2(ue.x + uo.x, ue.y + uo.y);
        sU[bm * 12 + g + 6] = make_float2(ue.x - uo.x, ue.y - uo.y);
    }
    __syncthreads();
    float part = 0.f;
    for (int t = tid; t < 864; t += 128) {
        int bq = t / 72, r = t % 72;
        int a = r / 12, g = r % 12;
        const float2* up = &sU[bq * 72 + g];
        float ve = up[0].x, vo = 0.f;
        #pragma unroll
        for (int m = 1; m < 6; ++m) {
            float2 u = up[m * 12];
            float2 e = sE12[(m + 5) * 12 + a];
            float tt = 2.f * (u.x * e.x - u.y * e.y);
            if (m & 1) vo += tt; else ve += tt;
        }
        float v0 = ve + vo, v1 = ve - vo;
        float s = 0.f;
        if (v0 > 0.f) s += v0;
        if (v1 > 0.f) s += v1;
        part += sw2[bq] * s;
    }
    sred[tid] = part;
    __syncthreads();
    for (int s = 64; s > 0; s >>= 1) {
        if (tid < s) sred[tid] += sred[tid + s];
        __syncthreads();
    }
    if (tid == 0) g_feat[zo] = sred[0] * (1.0f / 144.0f);
}

// ---------------- linear head ----------------
__global__ void k_lin(const float* __restrict__ w_lin, const float* __restrict__ b_lin,
                      float* __restrict__ out) {
    int t = blockIdx.x * blockDim.x + threadIdx.x;
    if (t >= BATCH * 10) return;
    int z = t / 10, f = t % 10;
    float acc = b_lin[f];
    #pragma unroll
    for (int o = 0; o < NF2; ++o)
        acc += g_feat[z * NF2 + o] * w_lin[f * NF2 + o];
    out[t] = acc;
}

// ---------------- launch ----------------
extern "C" void kernel_launch(void* const* d_in, const int* in_sizes, int n_in,
                              void* d_out, int out_size) {
    const float* x     = (const float*)d_in[0];
    const float* psi1  = (const float*)d_in[1];
    const float* psi2  = (const float*)d_in[2];
    const float* w_lin = (const float*)d_in[3];
    const float* b_lin = (const float*)d_in[4];
    float* out = (float*)d_out;

    k_setup<<<(SET_TAB_BASE + N_SET2 + 255) / 256, 256>>>();
    k_prep<<<PREP_TOTAL, 256>>>(psi1, psi2, x);
    k_mid<<<dim3(20, 20), 320>>>();
    k_Fx<<<BATCH * 20, 192>>>();
    k_Fo<<<dim3(21, BATCH / FO_ZT), 256>>>();
    k_final<<<BATCH * NF2, 128>>>();
    k_lin<<<(BATCH * 10 + 255) / 256, 256>>>(w_lin, b_lin, out);
}

// round 7
// speedup vs baseline: 3.5092x; 1.0200x over previous
#include <cuda_runtime.h>
#include <cuda_bf16.h>
#include <math.h>

#define PI_F 3.14159265358979323846f

#define BATCH 128
#define NF2 40

// ---------------- device tables ----------------
__device__ float  g_w2n[12];

__device__ float2 g_T60[10 * 60];        // e^{-2pi i m a/60}, m=0..9
__device__ float2 g_E20P[19 * 20];       // e^{+2pi i (ni-9) x/20}
__device__ float2 g_E20M[11 * 20];       // e^{-2pi i (mi-5) x/20}
__device__ float2 g_E12P[11 * 12];       // e^{+2pi i (ni-5) x/12}

__device__ float  g_wd_s2[10 * 60 * 10];     // [l][b][m]
__device__ float  g_d1w[10 * 20 * 10 * 19];  // [l][b][m][ni]
__device__ float  g_d12w[6 * 20 * 6 * 11];   // [l][b][m][ki]
__device__ float  g_d2w[6 * 12 * 6 * 11];    // [l][b][m][ni]
__device__ float2 g_Y1[10 * 24 * 19];        // [l][g][ni]
__device__ float2 g_D2[6 * 144 * 11 * 11];   // [l][g][ki][ni]

__device__ __align__(16) float2 g_E1[20 * 20 * 2000]; // [o][b][(m*20+g)*10+l]
__device__ __align__(16) float2 g_X[BATCH * 100];     // [z][m*10+l]
__device__ float2 g_Yg[(size_t)BATCH * 20 * 20 * 66]; // [z][c][b][m*11+ni]
__device__ __align__(16) float2 g_Fx[(size_t)128 * 3220]; // packed [p][z][ik]
__device__ __align__(16) float2 g_B2[316800];         // packed [l][ik][o*11+ni]
__device__ float2 g_Fo[(size_t)BATCH * NF2 * 21 * 11];// [z][o][p][ni]
__device__ float  g_feat[BATCH * NF2];

// p = (l,m) valid pairs, m<=l<=5
__constant__ int cPl[21]   = {0,1,1,2,2,2,3,3,3,3,4,4,4,4,4,5,5,5,5,5,5};
__constant__ int cPref[21] = {0,20,80,140,240,340,440,580,720,860,1000,1180,1360,1540,1720,1900,2120,2340,2560,2780,3000};
__constant__ int cOutOff[22] = {0,1,4,7,12,17,22,29,36,43,50,59,68,77,86,95,106,117,128,139,150,161};
__constant__ int cPm[21]   = {0,0,1,0,1,2,0,1,2,3,0,1,2,3,4,0,1,2,3,4,5};
__constant__ int cBl[36]  = {0,1,1,1,2,2,2,2,2,3,3,3,3,3,3,3,4,4,4,4,4,4,4,4,4,5,5,5,5,5,5,5,5,5,5,5};
__constant__ int cBkk[36] = {0,0,1,2,0,1,2,3,4,0,1,2,3,4,5,6,0,1,2,3,4,5,6,7,8,0,1,2,3,4,5,6,7,8,9,10};
// t -> (p, kk) lookup for k_Fx (t = cOutOff[p] + kk)
__constant__ signed char cT2P[161] = {
0,
1,1,1,
2,2,2,
3,3,3,3,3,
4,4,4,4,4,
5,5,5,5,5,
6,6,6,6,6,6,6,
7,7,7,7,7,7,7,
8,8,8,8,8,8,8,
9,9,9,9,9,9,9,
10,10,10,10,10,10,10,10,10,
11,11,11,11,11,11,11,11,11,
12,12,12,12,12,12,12,12,12,
13,13,13,13,13,13,13,13,13,
14,14,14,14,14,14,14,14,14,
15,15,15,15,15,15,15,15,15,15,15,
16,16,16,16,16,16,16,16,16,16,16,
17,17,17,17,17,17,17,17,17,17,17,
18,18,18,18,18,18,18,18,18,18,18,
19,19,19,19,19,19,19,19,19,19,19,
20,20,20,20,20,20,20,20,20,20,20};
__constant__ signed char cT2KK[161] = {
0,
0,1,2,
0,1,2,
0,1,2,3,4,
0,1,2,3,4,
0,1,2,3,4,
0,1,2,3,4,5,6,
0,1,2,3,4,5,6,
0,1,2,3,4,5,6,
0,1,2,3,4,5,6,
0,1,2,3,4,5,6,7,8,
0,1,2,3,4,5,6,7,8,
0,1,2,3,4,5,6,7,8,
0,1,2,3,4,5,6,7,8,
0,1,2,3,4,5,6,7,8,
0,1,2,3,4,5,6,7,8,9,10,
0,1,2,3,4,5,6,7,8,9,10,
0,1,2,3,4,5,6,7,8,9,10,
0,1,2,3,4,5,6,7,8,9,10,
0,1,2,3,4,5,6,7,8,9,10,
0,1,2,3,4,5,6,7,8,9,10};

__device__ __forceinline__ float fpow_i(float x, int p) {
    float r = 1.f;
    for (int i = 0; i < p; ++i) r *= x;
    return r;
}

__device__ float wigf(const float* lf, int l, int m, int n, float beta) {
    if (m > l || m < -l || n > l || n < -l) return 0.f;
    float cb = cosf(0.5f * beta), sb = sinf(0.5f * beta);
    float pref = 0.5f * (lf[l + m] + lf[l - m] + lf[l + n] + lf[l - n]);
    int s0 = max(0, n - m), s1 = min(l + n, l - m);
    float acc = 0.f;
    for (int s = s0; s <= s1; ++s) {
        float c = pref - (lf[l + n - s] + lf[s] + lf[m - n + s] + lf[l - m - s]);
        float t = expf(c) * fpow_i(cb, 2 * l + n - m - 2 * s) * fpow_i(sb, m - n + 2 * s);
        acc += ((m - n + s) & 1) ? -t : t;
    }
    return acc;
}

__device__ float dh_w_f(int bsz, int k) {
    float beta = PI_F * (2 * k + 1) / (4.0f * bsz);
    float s = 0.0f;
    for (int j = 0; j < bsz; ++j)
        s += sinf((2 * j + 1) * beta) / (2 * j + 1);
    return (2.0f / bsz) * sinf(beta) * s;
}

// ---------------- merged setup (all fp32) ----------------
#define O_D1W  6000
#define O_D12W 44000
#define O_D2W  51920
#define O_Y1s  56672
#define O_D2s  61232
#define N_SET2 165776
#define SET_TAB_BASE 2048

__global__ void k_setup() {
    __shared__ float s_lf[64];
    int tid = threadIdx.x;
    if (tid < 64) s_lf[tid] = lgammaf(tid + 1.0f);
    __syncthreads();
    int idx = blockIdx.x * blockDim.x + tid;
    if (idx < 1344) {
        if (idx < 600) {
            int m = idx / 60, a = idx % 60;
            float th = -2.0f * PI_F * m * a / 60.0f;
            float sn, cs; sincosf(th, &sn, &cs);
            g_T60[idx] = make_float2(cs, sn);
        } else if (idx < 980) {
            int r = idx - 600; int ni = r / 20, x = r % 20;
            float th = 2.0f * PI_F * (ni - 9) * x / 20.0f;
            float sn, cs; sincosf(th, &sn, &cs);
            g_E20P[r] = make_float2(cs, sn);
        } else if (idx < 1200) {
            int r = idx - 980; int mi = r / 20, x = r % 20;
            float th = -2.0f * PI_F * (mi - 5) * x / 20.0f;
            float sn, cs; sincosf(th, &sn, &cs);
            g_E20M[r] = make_float2(cs, sn);
        } else if (idx < 1332) {
            int r = idx - 1200; int ni = r / 12, x = r % 12;
            float th = 2.0f * PI_F * (ni - 5) * x / 12.0f;
            float sn, cs; sincosf(th, &sn, &cs);
            g_E12P[r] = make_float2(cs, sn);
        } else {
            int k = idx - 1332;
            float s = 0.0f;
            for (int j = 0; j < 12; ++j) s += dh_w_f(6, j);
            g_w2n[k] = dh_w_f(6, k) / s;
        }
        return;
    }
    if (idx < SET_TAB_BASE) return;
    int i2 = idx - SET_TAB_BASE;
    if (i2 >= N_SET2) return;
    if (i2 < O_D1W) {
        int i = i2;
        int l = i / 600, b = (i % 600) / 10, m = i % 10;
        float beta = PI_F * (2 * b + 1) / 120.0f;
        g_wd_s2[i] = dh_w_f(30, b) * wigf(s_lf, l, m, 0, beta);
    } else if (i2 < O_D12W) {
        int i = i2 - O_D1W;
        int l = i / 3800; int r = i % 3800;
        int b = r / 190; int q = r % 190;
        int m = q / 19, ni = q % 19;
        float beta = PI_F * (2 * b + 1) / 40.0f;
        g_d1w[i] = (2 * l + 1) * wigf(s_lf, l, m, ni - 9, beta);
    } else if (i2 < O_D2W) {
        int i = i2 - O_D12W;
        int l = i / 1320; int r = i % 1320;
        int b = r / 66; int q = r % 66;
        int m = q / 11, ki = q % 11;
        float beta = PI_F * (2 * b + 1) / 40.0f;
        g_d12w[i] = dh_w_f(10, b) * wigf(s_lf, l, m, ki - 5, beta);
    } else if (i2 < O_Y1s) {
        int i = i2 - O_D2W;
        int l = i / 792; int r = i % 792;
        int b = r / 66; int q = r % 66;
        int m = q / 11, ni = q % 11;
        float beta = PI_F * (2 * b + 1) / 24.0f;
        g_d2w[i] = (2 * l + 1) * wigf(s_lf, l, m, ni - 5, beta);
    } else if (i2 < O_D2s) {
        int i = i2 - O_Y1s;
        int l = i / (24 * 19); int r = i % (24 * 19);
        int g = r / 19, mi = r % 19;
        int ib = g / 8, ja = g % 8;
        float beta = (ib + 1) * PI_F / 24.0f;
        float alpha = 2.0f * PI_F * ja / 8.0f;
        int m = mi - 9;
        float d = wigf(s_lf, l, m, 0, beta);
        float th = -(float)m * alpha;
        float sn, cs; sincosf(th, &sn, &cs);
        g_Y1[i] = make_float2(d * cs, d * sn);
    } else {
        int i = i2 - O_D2s;
        int l = i / (144 * 121); int r = i % (144 * 121);
        int g = r / 121; int q = r % 121;
        int ki = q / 11, ni = q % 11;
        int ib = g / 48, ja = (g / 6) % 8, kg = g % 6;
        float beta = (ib + 1) * PI_F / 24.0f;
        float alpha = 2.0f * PI_F * ja / 8.0f;
        float gamma = 2.0f * PI_F * kg / 6.0f;
        int m = ki - 5, n = ni - 5;
        float d = wigf(s_lf, l, m, n, beta);
        float th = -((float)m * alpha + (float)n * gamma);
        float sn, cs; sincosf(th, &sn, &cs);
        g_D2[i] = make_float2(d * cs, d * sn);
    }
}

// ---------------- merged prep: E1 (blocks 0..399), B2 (400..1839), X (1840..1967) ----------------
#define PREP_E1_N 400
#define PREP_B2_N 1440
#define PREP_X_BASE (PREP_E1_N + PREP_B2_N)
#define PREP_TOTAL (PREP_X_BASE + BATCH)

__global__ __launch_bounds__(256) void k_prep(const float* __restrict__ psi1,
                                              const float* __restrict__ psi2,
                                              const float* __restrict__ x) {
    __shared__ __align__(16) char sbuf[24576];
    int blk = blockIdx.x;
    int tid = threadIdx.x;

    if (blk < PREP_E1_N) {
        int b = blk % 20, o = blk / 20;
        float2* sPsi  = (float2*)sbuf;                 // 190
        float*  sd1w  = (float*)(sbuf + 1520);         // 1900
        float2* sE20P = (float2*)(sbuf + 9120);        // 380
        for (int t = tid; t < 190; t += 256) {
            int l = t / 19, ni = t % 19;
            float2 acc = make_float2(0.f, 0.f);
            for (int g = 0; g < 24; ++g) {
                float w = psi1[o * 24 + g];
                float2 y = g_Y1[(l * 24 + g) * 19 + ni];
                acc.x += w * y.x; acc.y += w * y.y;
            }
            sPsi[t] = acc;
        }
        for (int t = tid; t < 1900; t += 256) {
            int l = t / 190, m = (t / 19) % 10, ni = t % 19;
            sd1w[t] = g_d1w[((l * 20 + b) * 10 + m) * 19 + ni];
        }
        for (int t = tid; t < 380; t += 256) sE20P[t] = g_E20P[t];
        __syncthreads();
        for (int t = tid; t < 2000; t += 256) {
            int l = t % 10;
            int g = (t / 10) % 20;
            int m = t / 200;
            float2 acc = make_float2(0.f, 0.f);
            const float* dw = &sd1w[(l * 10 + m) * 19];
            const float2* ps = &sPsi[l * 19];
            for (int ni = 0; ni < 19; ++ni) {
                float d = dw[ni];
                float2 p = ps[ni];
                float2 e = sE20P[ni * 20 + g];
                acc.x += d * (p.x * e.x - p.y * e.y);
                acc.y += d * (p.x * e.y + p.y * e.x);
            }
            g_E1[(size_t)(o * 20 + b) * 2000 + t] = acc;
        }
    } else if (blk < PREP_X_BASE) {
        int q = blk - PREP_E1_N;
        int s = q / 40, rg = q % 40;
        int l = cBl[s], kk = cBkk[s];
        int kidx = kk - l + 5;
        float2* sD = (float2*)sbuf;                    // 1584
        float*  sP = (float*)(sbuf + 12672);           // 20*145
        for (int t = tid; t < 1584; t += 256) {
            int g = t / 11, ni = t % 11;
            sD[t] = g_D2[((l * 144 + g) * 11 + kidx) * 11 + ni];
        }
        int row0 = rg * 20;
        for (int t = tid; t < 20 * 144; t += 256) {
            int r = t / 144, g = t % 144;
            sP[r * 145 + g] = psi2[(size_t)(row0 + r) * 144 + g];
        }
        __syncthreads();
        if (tid < 220) {
            int rl = tid / 11, ni = tid % 11;
            int pr = row0 + rl;
            float2 acc = make_float2(0.f, 0.f);
            const float* pp = &sP[rl * 145];
            #pragma unroll 8
            for (int g = 0; g < 144; ++g) {
                float w = pp[g];
                float2 d = sD[g * 11 + ni];
                acc.x += w * d.x; acc.y += w * d.y;
            }
            int i = pr / 40, o = pr % 40;
            g_B2[(size_t)8800 * l * l + (size_t)(i * (2 * l + 1) + kk) * 440 + o * 11 + ni] = acc;
        }
    } else {
        int z = blk - PREP_X_BASE;
        float*  sx  = (float*)sbuf;                    // 3600
        float2* sxf = (float2*)(sbuf + 14400);         // 600
        for (int t = tid; t < 3600; t += 256)
            sx[t] = x[(size_t)z * 3600 + t];
        __syncthreads();
        for (int t = tid; t < 600; t += 256) {
            int b = t / 10, m = t % 10;
            float re = 0.f, im = 0.f;
            const float* row = &sx[b * 60];
            const float2* tw = &g_T60[m * 60];
            for (int a = 0; a < 60; ++a) {
                float v = row[a];
                re += v * tw[a].x; im += v * tw[a].y;
            }
            sxf[t] = make_float2(re, im);
        }
        __syncthreads();
        for (int t = tid; t < 100; t += 256) {
            int l = t / 10, m = t % 10;
            float2 acc = make_float2(0.f, 0.f);
            for (int b = 0; b < 60; ++b) {
                float w = g_wd_s2[(l * 60 + b) * 10 + m];
                float2 v = sxf[b * 10 + m];
                acc.x += w * v.x; acc.y += w * v.y;
            }
            g_X[z * 100 + m * 10 + l] = acc;
        }
    }
}

// ---------------- fused mid (radix-2, in-place A butterfly) ----------------
__global__ __launch_bounds__(320) void k_mid() {
    __shared__ __align__(16) float2 sE1[2000]; // [m][g][l]
    __shared__ float2 sTw1[200];               // [m][a], x2 m>=1
    __shared__ float2 sEm[220];                // [mi][x]
    __shared__ __align__(16) float2 sX[1600];  // [zz][m*10+l]
    __shared__ float2 sA[1920];                // [zz][m2*20+g]
    int b = blockIdx.x, c = blockIdx.y;
    int tid = threadIdx.x;
    const float2* e1 = g_E1 + (size_t)(c * 20 + b) * 2000;
    for (int t = tid; t < 2000; t += 320) sE1[t] = e1[t];
    for (int t = tid; t < 200; t += 320) {
        int m = t / 20;
        float2 e = g_E20P[(m + 9) * 20 + t % 20];
        float s = (m >= 1) ? 2.f : 1.f;
        sTw1[t] = make_float2(s * e.x, s * e.y);
    }
    for (int t = tid; t < 220; t += 320) sEm[t] = g_E20M[t];
    __syncthreads();
    int zz = tid / 20, g = tid % 20;
    for (int stage = 0; stage < 8; ++stage) {
        int z0 = stage * 16;
        for (int t = tid; t < 1600; t += 320)
            sX[t] = g_X[(z0 + t / 100) * 100 + t % 100];
        __syncthreads();
        float2 S1m[10];
        #pragma unroll
        for (int m = 0; m < 10; ++m) {
            const float4* xp = (const float4*)&sX[zz * 100 + m * 10];
            const float4* ep = (const float4*)&sE1[(m * 20 + g) * 10];
            float ar = 0.f, ai = 0.f;
            #pragma unroll
            for (int i = 0; i < 5; ++i) {
                float4 xv = xp[i];
                float4 ev = ep[i];
                ar += xv.x * ev.x - xv.y * ev.y;
                ai += xv.x * ev.y + xv.y * ev.x;
                ar += xv.z * ev.z - xv.w * ev.w;
                ai += xv.z * ev.w + xv.w * ev.z;
            }
            S1m[m] = make_float2(ar, ai);
        }
        float ys[10], yd[10];
        #pragma unroll
        for (int a = 0; a < 10; ++a) {
            float ve = S1m[0].x, vo = 0.f;
            #pragma unroll
            for (int m = 1; m < 10; ++m) {
                float2 e = sTw1[m * 20 + a];
                float tt = S1m[m].x * e.x - S1m[m].y * e.y;
                if (m & 1) vo += tt; else ve += tt;
            }
            float y0 = fmaxf(ve + vo, 0.f);
            float y1 = fmaxf(ve - vo, 0.f);
            ys[a] = y0 + y1;
            yd[a] = y0 - y1;
        }
        #pragma unroll
        for (int m2 = 0; m2 < 6; ++m2) {
            const float2* ep = &sEm[(m2 + 5) * 20];
            const float* yy = (m2 & 1) ? yd : ys;
            float ar = 0.f, ai = 0.f;
            #pragma unroll
            for (int a = 0; a < 10; ++a) {
                ar += yy[a] * ep[a].x;
                ai += yy[a] * ep[a].y;
            }
            sA[zz * 120 + m2 * 20 + g] = make_float2(ar, ai);
        }
        __syncthreads();
        for (int t = tid; t < 960; t += 320) {
            int zz2 = t / 60, m2 = (t / 10) % 6, a = t % 10;
            int base = zz2 * 120 + m2 * 20;
            float2 p = sA[base + a];
            float2 q = sA[base + a + 10];
            sA[base + a]      = make_float2(p.x + q.x, p.y + q.y);
            sA[base + a + 10] = make_float2(p.x - q.x, p.y - q.y);
        }
        __syncthreads();
        for (int t = tid; t < 1056; t += 320) {
            int zz2 = t / 66, r = t % 66;
            int m = r / 11, ni = r % 11;
            int odd = (ni - 5) & 1;
            const float2* ap = &sA[zz2 * 120 + m * 20 + odd * 10];
            const float2* ep = &sEm[ni * 20];
            float2 acc = make_float2(0.f, 0.f);
            #pragma unroll
            for (int gg = 0; gg < 10; ++gg) {
                float2 av = ap[gg], e = ep[gg];
                acc.x += av.x * e.x - av.y * e.y;
                acc.y += av.x * e.y + av.y * e.x;
            }
            int z = z0 + zz2;
            g_Yg[((size_t)((z * 20 + c) * 20 + b)) * 66 + r] = acc;
        }
        __syncthreads();
    }
}

// ---------------- Fx packed (lookup-table index) ----------------
__global__ void k_Fx() {
    __shared__ float2 sYs[1320]; // [b][m*11+ni]
    int zi = blockIdx.x;
    int z = zi / 20, i = zi % 20;
    for (int t = threadIdx.x; t < 1320; t += blockDim.x)
        sYs[t] = g_Yg[(size_t)zi * 1320 + t];
    __syncthreads();
    int t = threadIdx.x;
    if (t < 161) {
        int p = cT2P[t];
        int kk = cT2KK[t];
        int l = cPl[p], m = cPm[p];
        int kidx = kk - l + 5;
        float2 acc = make_float2(0.f, 0.f);
        #pragma unroll
        for (int b = 0; b < 20; ++b) {
            float d = g_d12w[((l * 20 + b) * 6 + m) * 11 + kidx];
            float2 v = sYs[b * 66 + m * 11 + kidx];
            acc.x += d * v.x; acc.y += d * v.y;
        }
        int Kl = 20 * (2 * l + 1);
        g_Fx[(size_t)cPref[p] * 128 + (size_t)z * Kl + i * (2 * l + 1) + kk] = acc;
    }
}

// ---------------- Fo GEMM (heavy-l first, ik-paired float4) ----------------
#define FO_ZT 8
__global__ void k_Fo() {
    __shared__ __align__(16) float2 sAa[FO_ZT * 220];
    int p = 20 - blockIdx.x;
    int z0 = blockIdx.y * FO_ZT;
    int l = cPl[p];
    int Kl = 20 * (2 * l + 1);
    size_t abase = (size_t)cPref[p] * 128 + (size_t)z0 * Kl;
    for (int t = threadIdx.x; t < FO_ZT * Kl; t += blockDim.x)
        sAa[t] = g_Fx[abase + t];
    __syncthreads();
    int t = threadIdx.x;
    if (t < 220) {
        float2 a0[FO_ZT], a1[FO_ZT];
        #pragma unroll
        for (int zz = 0; zz < FO_ZT; ++zz) { a0[zz] = make_float2(0.f, 0.f); a1[zz] = make_float2(0.f, 0.f); }
        const float4* Bp = (const float4*)(g_B2 + (size_t)8800 * l * l);
        const float4* Ap = (const float4*)sAa;
        for (int ik = 0; ik < Kl; ik += 2) {
            float4 b0 = Bp[ik * 220 + t];
            float4 b1 = Bp[(ik + 1) * 220 + t];
            #pragma unroll
            for (int zz = 0; zz < FO_ZT; ++zz) {
                float4 av = Ap[(zz * Kl + ik) >> 1];
                a0[zz].x += av.x * b0.x - av.y * b0.y;
                a0[zz].y += av.x * b0.y + av.y * b0.x;
                a1[zz].x += av.x * b0.z - av.y * b0.w;
                a1[zz].y += av.x * b0.w + av.y * b0.z;
                a0[zz].x += av.z * b1.x - av.w * b1.y;
                a0[zz].y += av.z * b1.y + av.w * b1.x;
                a1[zz].x += av.z * b1.z - av.w * b1.w;
                a1[zz].y += av.z * b1.w + av.w * b1.z;
            }
        }
        int o0 = (2 * t) / 11, n0 = (2 * t) % 11;
        int o1 = (2 * t + 1) / 11, n1 = (2 * t + 1) % 11;
        #pragma unroll
        for (int zz = 0; zz < FO_ZT; ++zz) {
            int z = z0 + zz;
            g_Fo[((size_t)(z * 40 + o0) * 21 + p) * 11 + n0] = a0[zz];
            g_Fo[((size_t)(z * 40 + o1) * 21 + p) * 11 + n1] = a1[zz];
        }
    }
}

// ---------------- final (radix-2 on both 12-pt stages) ----------------
__global__ void k_final() {
    __shared__ float2 sFo[231];
    __shared__ float2 sE12[132];
    __shared__ float2 sFh2[792];
    __shared__ float2 sU[864];
    __shared__ float  sw2[12];
    __shared__ float  sred[128];
    int zo = blockIdx.x;
    int tid = threadIdx.x;
    for (int t = tid; t < 231; t += 128) sFo[t] = g_Fo[(size_t)zo * 231 + t];
    for (int t = tid; t < 132; t += 128) sE12[t] = g_E12P[t];
    if (tid < 12) sw2[tid] = g_w2n[tid];
    __syncthreads();
    for (int t = tid; t < 792; t += 128) {
        int b = t / 66, r = t % 66;
        int m = r / 11, ni = r % 11;
        float2 acc = make_float2(0.f, 0.f);
        for (int l = m; l < 6; ++l) {
            float d = g_d2w[((l * 12 + b) * 6 + m) * 11 + ni];
            float2 f = sFo[(l * (l + 1) / 2 + m) * 11 + ni];
            acc.x += d * f.x; acc.y += d * f.y;
        }
        sFh2[(b * 6 + m) * 11 + ni] = acc;
    }
    __syncthreads();
    for (int t = tid; t < 432; t += 128) {
        int bm = t / 6, g = t % 6;
        float2 ue = make_float2(0.f, 0.f), uo = make_float2(0.f, 0.f);
        const float2* fp = &sFh2[bm * 11];
        #pragma unroll
        for (int ni = 0; ni < 11; ++ni) {
            float2 f = fp[ni];
            float2 e = sE12[ni * 12 + g];
            float tr = f.x * e.x - f.y * e.y;
            float ti = f.x * e.y + f.y * e.x;
            if ((ni - 5) & 1) { uo.x += tr; uo.y += ti; }
            else              { ue.x += tr; ue.y += ti; }
        }
        sU[bm * 12 + g]     = make_float2(ue.x + uo.x, ue.y + uo.y);
        sU[bm * 12 + g + 6] = make_float2(ue.x - uo.x, ue.y - uo.y);
    }
    __syncthreads();
    float part = 0.f;
    for (int t = tid; t < 864; t += 128) {
        int bq = t / 72, r = t % 72;
        int a = r / 12, g = r % 12;
        const float2* up = &sU[bq * 72 + g];
        float ve = up[0].x, vo = 0.f;
        #pragma unroll
        for (int m = 1; m < 6; ++m) {
            float2 u = up[m * 12];
            float2 e = sE12[(m + 5) * 12 + a];
            float tt = 2.f * (u.x * e.x - u.y * e.y);
            if (m & 1) vo += tt; else ve += tt;
        }
        float v0 = ve + vo, v1 = ve - vo;
        float s = 0.f;
        if (v0 > 0.f) s += v0;
        if (v1 > 0.f) s += v1;
        part += sw2[bq] * s;
    }
    sred[tid] = part;
    __syncthreads();
    for (int s = 64; s > 0; s >>= 1) {
        if (tid < s) sred[tid] += sred[tid + s];
        __syncthreads();
    }
    if (tid == 0) g_feat[zo] = sred[0] * (1.0f / 144.0f);
}

// ---------------- linear head ----------------
__global__ void k_lin(const float* __restrict__ w_lin, const float* __restrict__ b_lin,
                      float* __restrict__ out) {
    int t = blockIdx.x * blockDim.x + threadIdx.x;
    if (t >= BATCH * 10) return;
    int z = t / 10, f = t % 10;
    float acc = b_lin[f];
    #pragma unroll
    for (int o = 0; o < NF2; ++o)
        acc += g_feat[z * NF2 + o] * w_lin[f * NF2 + o];
    out[t] = acc;
}

// ---------------- launch ----------------
extern "C" void kernel_launch(void* const* d_in, const int* in_sizes, int n_in,
                              void* d_out, int out_size) {
    const float* x     = (const float*)d_in[0];
    const float* psi1  = (const float*)d_in[1];
    const float* psi2  = (const float*)d_in[2];
    const float* w_lin = (const float*)d_in[3];
    const float* b_lin = (const float*)d_in[4];
    float* out = (float*)d_out;

    k_setup<<<(SET_TAB_BASE + N_SET2 + 255) / 256, 256>>>();
    k_prep<<<PREP_TOTAL, 256>>>(psi1, psi2, x);
    k_mid<<<dim3(20, 20), 320>>>();
    k_Fx<<<BATCH * 20, 192>>>();
    k_Fo<<<dim3(21, BATCH / FO_ZT), 256>>>();
    k_final<<<BATCH * NF2, 128>>>();
    k_lin<<<(BATCH * 10 + 255) / 256, 256>>>(w_lin, b_lin, out);
}